// round 4
// baseline (speedup 1.0000x reference)
#include <cuda_runtime.h>
#include <math.h>
#include <stdint.h>

#define D_NUM 4000
#define T_NUM 2000
#define FEAT  256
#define UNITS 200
#define TOPK  10
#define NCHUNK 16

// ---------------- scratch (device globals; no runtime allocation) ----------------
__device__ float g_S[(size_t)D_NUM * T_NUM];
__device__ float g_catd[(size_t)D_NUM * 3 * FEAT];
__device__ float g_catt[(size_t)T_NUM * 3 * FEAT];
__device__ float g_hd[(size_t)D_NUM * FEAT];
__device__ float g_ht[(size_t)T_NUM * FEAT];
__device__ float g_hdp[(size_t)D_NUM * UNITS];
__device__ float g_htp[(size_t)T_NUM * UNITS];
__device__ float g_sd[D_NUM];
__device__ float g_st[T_NUM];
__device__ float g_nd[D_NUM];
__device__ float g_nt[T_NUM];
__device__ float g_ntraw[T_NUM];
__device__ float g_part[NCHUNK * T_NUM];
__device__ int   g_selidx[D_NUM * TOPK];
__device__ float g_selval[D_NUM * TOPK];

// ---------------- reductions ----------------
__global__ void rowsum_rsqrt(const float* __restrict__ A, int rows, int cols,
                             float* __restrict__ out) {
    int row = blockIdx.x;
    if (row >= rows) return;
    const float* a = A + (size_t)row * cols;
    float s = 0.f;
    for (int j = threadIdx.x; j < cols; j += blockDim.x) s += a[j];
    __shared__ float red[256];
    red[threadIdx.x] = s;
    __syncthreads();
    for (int off = 128; off > 0; off >>= 1) {
        if (threadIdx.x < off) red[threadIdx.x] += red[threadIdx.x + off];
        __syncthreads();
    }
    if (threadIdx.x == 0) {
        float n = red[0];
        if (n == 0.f) n = 1.f;
        out[row] = rsqrtf(n);
    }
}

__global__ void colsum_partial(const float* __restrict__ A, int rows, int cols,
                               float* __restrict__ part) {
    int j = blockIdx.x * blockDim.x + threadIdx.x;
    if (j >= cols) return;
    int chunk = (rows + NCHUNK - 1) / NCHUNK;
    int r0 = blockIdx.y * chunk;
    int r1 = r0 + chunk; if (r1 > rows) r1 = rows;
    float s = 0.f;
    for (int i = r0; i < r1; i++) s += A[(size_t)i * cols + j];
    part[blockIdx.y * cols + j] = s;
}

__global__ void colsum_finish(const float* __restrict__ part, int cols,
                              float* __restrict__ out) {
    int j = blockIdx.x * blockDim.x + threadIdx.x;
    if (j >= cols) return;
    float s = 0.f;
    for (int c = 0; c < NCHUNK; c++) s += part[c * cols + j];
    if (s == 0.f) s = 1.f;
    out[j] = rsqrtf(s);
}

// ---------------- small utility kernels ----------------
__global__ void zero_vec(float* __restrict__ p, int n) {
    int i = blockIdx.x * blockDim.x + threadIdx.x;
    if (i < n) p[i] = 0.f;
}

__global__ void zero_strided(float* __restrict__ dst, int ld, int rows, int cols) {
    int c = blockIdx.x * blockDim.x + threadIdx.x;
    int r = blockIdx.y;
    if (c < cols && r < rows) dst[(size_t)r * ld + c] = 0.f;
}

__global__ void relu_strided(float* __restrict__ dst, int ld, int rows, int cols) {
    int c = blockIdx.x * blockDim.x + threadIdx.x;
    int r = blockIdx.y;
    if (c < cols && r < rows) {
        size_t o = (size_t)r * ld + c;
        dst[o] = fmaxf(dst[o], 0.f);
    }
}

__global__ void copy_strided(float* __restrict__ dst, int ldd,
                             const float* __restrict__ src, int lds,
                             int rows, int cols) {
    int c = blockIdx.x * blockDim.x + threadIdx.x;
    int r = blockIdx.y;
    if (c < cols && r < rows)
        dst[(size_t)r * ldd + c] = src[(size_t)r * lds + c];
}

// ---------------- top-k (exact stable-sort tie semantics: min index wins) -------
__global__ void topk_kernel(const float* __restrict__ S,
                            int* __restrict__ selidx, float* __restrict__ selval,
                            float* __restrict__ nd_out, float* __restrict__ ntraw) {
    __shared__ float sv[T_NUM];
    __shared__ float rv[256];
    __shared__ int   ri[256];
    __shared__ int   sel[TOPK];
    __shared__ float selv[TOPK];
    int row = blockIdx.x;
    const float* srow = S + (size_t)row * T_NUM;
    for (int j = threadIdx.x; j < T_NUM; j += 256) sv[j] = srow[j];
    __syncthreads();
    for (int it = 0; it < TOPK; it++) {
        float best = -3.f; int bidx = T_NUM;
        for (int j = threadIdx.x; j < T_NUM; j += 256) {
            float v = sv[j];
            if (v > best || (v == best && j < bidx)) { best = v; bidx = j; }
        }
        rv[threadIdx.x] = best; ri[threadIdx.x] = bidx;
        __syncthreads();
        for (int off = 128; off > 0; off >>= 1) {
            if (threadIdx.x < off) {
                float v2 = rv[threadIdx.x + off]; int i2 = ri[threadIdx.x + off];
                if (v2 > rv[threadIdx.x] ||
                    (v2 == rv[threadIdx.x] && i2 < ri[threadIdx.x])) {
                    rv[threadIdx.x] = v2; ri[threadIdx.x] = i2;
                }
            }
            __syncthreads();
        }
        if (threadIdx.x == 0) {
            sel[it] = ri[0]; selv[it] = rv[0];
            sv[ri[0]] = -2.f;
        }
        __syncthreads();
    }
    if (threadIdx.x < TOPK) {
        selidx[row * TOPK + threadIdx.x] = sel[threadIdx.x];
        selval[row * TOPK + threadIdx.x] = selv[threadIdx.x];
        atomicAdd(&ntraw[sel[threadIdx.x]], selv[threadIdx.x]);
    }
    if (threadIdx.x == 0) {
        float s = 0.f;
        #pragma unroll
        for (int t = 0; t < TOPK; t++) s += selv[t];
        if (s == 0.f) s = 1.f;
        nd_out[row] = rsqrtf(s);
    }
}

__global__ void nt_finish(const float* __restrict__ raw, float* __restrict__ out, int n) {
    int i = blockIdx.x * blockDim.x + threadIdx.x;
    if (i < n) {
        float s = raw[i];
        if (s == 0.f) s = 1.f;
        out[i] = rsqrtf(s);
    }
}

// ---------------- sparse CGC kernels ----------------
__global__ void gather_dt(const int* __restrict__ selidx, const float* __restrict__ selval,
                          const float* __restrict__ nd, const float* __restrict__ nt,
                          const float* __restrict__ ht, int F,
                          float* __restrict__ outd, int ldo) {
    int d = blockIdx.x;
    __shared__ int   ci[TOPK];
    __shared__ float cw[TOPK];
    if (threadIdx.x < TOPK) {
        int c = selidx[d * TOPK + threadIdx.x];
        ci[threadIdx.x] = c;
        cw[threadIdx.x] = selval[d * TOPK + threadIdx.x] * nt[c];
    }
    __syncthreads();
    float ndv = nd[d];
    for (int f = threadIdx.x; f < F; f += blockDim.x) {
        float s = 0.f;
        #pragma unroll
        for (int j = 0; j < TOPK; j++) s += cw[j] * ht[(size_t)ci[j] * F + f];
        outd[(size_t)d * ldo + f] = fmaxf(s * ndv, 0.f);
    }
}

__global__ void scatter_td(const int* __restrict__ selidx, const float* __restrict__ selval,
                           const float* __restrict__ nd, const float* __restrict__ nt,
                           const float* __restrict__ hd, int F,
                           float* __restrict__ outt, int ldo) {
    int e = blockIdx.x;
    int d = e / TOPK;
    int t = selidx[e];
    float w = selval[e] * nd[d] * nt[t];
    const float* src = hd + (size_t)d * F;
    float* dst = outt + (size_t)t * ldo;
    for (int f = threadIdx.x; f < F; f += blockDim.x)
        atomicAdd(&dst[f], w * src[f]);
}

// ---------------- TF32 tensor-core GEMM, software pipelined ----------------
// C = EPI( rowscale[m] * sum_k ( A(m,k)*kscale[k] ) * B(k,n) )
// TA: A stored [K,M].  TB: B stored [N,K].  EPI: 0 none, 1 relu, 2 sigmoid.
// Block 128x64x16, double-buffered smem, register-staged global loads.

__device__ __forceinline__ uint32_t f2tf(float x) {
    uint32_t r;
    asm("cvt.rna.tf32.f32 %0, %1;" : "=r"(r) : "f"(x));
    return r;
}

__device__ __forceinline__ void mma_tf32(float c[4], uint32_t a0, uint32_t a1,
                                         uint32_t a2, uint32_t a3,
                                         uint32_t b0, uint32_t b1) {
    asm volatile(
        "mma.sync.aligned.m16n8k8.row.col.f32.tf32.tf32.f32 "
        "{%0,%1,%2,%3}, {%4,%5,%6,%7}, {%8,%9}, {%0,%1,%2,%3};"
        : "+f"(c[0]), "+f"(c[1]), "+f"(c[2]), "+f"(c[3])
        : "r"(a0), "r"(a1), "r"(a2), "r"(a3), "r"(b0), "r"(b1));
}

#define GBM 128
#define GBN 64
#define GBK 16
#define ASTR (GBK + 4)   // 20: conflict-free frag reads
#define BSTR (GBN + 8)   // 72: conflict-free frag reads

template <bool TA, bool TB, int EPI>
__global__ __launch_bounds__(256)
void mma_gemm(const float* __restrict__ A, const float* __restrict__ B,
              float* __restrict__ C,
              int M, int N, int K, int lda, int ldb, int ldc,
              const float* __restrict__ rowscale,
              const float* __restrict__ kscale) {
    __shared__ uint32_t As[2][GBM][ASTR];
    __shared__ uint32_t Bs[2][GBK][BSTR];

    int tid = threadIdx.x;
    int lane = tid & 31;
    int warp = tid >> 5;
    int gid = lane >> 2, tig = lane & 3;
    int mw = (warp & 3) * 32;
    int nw = (warp >> 2) * 32;
    int bm = blockIdx.y * GBM;
    int bn = blockIdx.x * GBN;

    float acc[2][4][4];
    #pragma unroll
    for (int i = 0; i < 2; i++)
        #pragma unroll
        for (int j = 0; j < 4; j++)
            #pragma unroll
            for (int l = 0; l < 4; l++) acc[i][j][l] = 0.f;

    float ra[8];
    float rb[4];

    int nkt = (K + GBK - 1) / GBK;

    // ---------- staging helpers (inlined by templates) ----------
    auto load_regs = [&](int kt) {
        int k0 = kt * GBK;
        if (!TA) {
            int m0 = tid >> 2;
            int kq = (tid & 3) * 4;
            int gk = k0 + kq;
            #pragma unroll
            for (int p = 0; p < 2; p++) {
                int gm = bm + m0 + p * 64;
                float4 v = make_float4(0.f, 0.f, 0.f, 0.f);
                if (gm < M && gk < K)
                    v = *reinterpret_cast<const float4*>(&A[(size_t)gm * lda + gk]);
                if (kscale && gk < K) {
                    v.x *= kscale[gk];     v.y *= kscale[gk + 1];
                    v.z *= kscale[gk + 2]; v.w *= kscale[gk + 3];
                }
                ra[p * 4 + 0] = v.x; ra[p * 4 + 1] = v.y;
                ra[p * 4 + 2] = v.z; ra[p * 4 + 3] = v.w;
            }
        } else {
            int kq = tid >> 5;          // 0..7
            int m4 = (tid & 31) * 4;
            #pragma unroll
            for (int p = 0; p < 2; p++) {
                int gk = k0 + kq + p * 8;
                int gm = bm + m4;
                float4 v = make_float4(0.f, 0.f, 0.f, 0.f);
                if (gk < K && gm < M)
                    v = *reinterpret_cast<const float4*>(&A[(size_t)gk * lda + gm]);
                if (kscale && gk < K) {
                    float ks = kscale[gk];
                    v.x *= ks; v.y *= ks; v.z *= ks; v.w *= ks;
                }
                ra[p * 4 + 0] = v.x; ra[p * 4 + 1] = v.y;
                ra[p * 4 + 2] = v.z; ra[p * 4 + 3] = v.w;
            }
        }
        if (!TB) {
            int kb = tid >> 4;
            int nq = (tid & 15) * 4;
            int gk = k0 + kb;
            int gn = bn + nq;
            float4 v = make_float4(0.f, 0.f, 0.f, 0.f);
            if (gk < K && gn < N)
                v = *reinterpret_cast<const float4*>(&B[(size_t)gk * ldb + gn]);
            rb[0] = v.x; rb[1] = v.y; rb[2] = v.z; rb[3] = v.w;
        } else {
            int nq = tid >> 2;
            int kb = (tid & 3) * 4;
            int gn = bn + nq;
            int gk = k0 + kb;
            float4 v = make_float4(0.f, 0.f, 0.f, 0.f);
            if (gn < N && gk < K)
                v = *reinterpret_cast<const float4*>(&B[(size_t)gn * ldb + gk]);
            rb[0] = v.x; rb[1] = v.y; rb[2] = v.z; rb[3] = v.w;
        }
    };

    auto store_smem = [&](int buf) {
        if (!TA) {
            int m0 = tid >> 2;
            int kq = (tid & 3) * 4;
            #pragma unroll
            for (int p = 0; p < 2; p++) {
                uint4 t4;
                t4.x = f2tf(ra[p * 4 + 0]); t4.y = f2tf(ra[p * 4 + 1]);
                t4.z = f2tf(ra[p * 4 + 2]); t4.w = f2tf(ra[p * 4 + 3]);
                *reinterpret_cast<uint4*>(&As[buf][m0 + p * 64][kq]) = t4;
            }
        } else {
            int kq = tid >> 5;
            int m4 = (tid & 31) * 4;
            #pragma unroll
            for (int p = 0; p < 2; p++) {
                int k = kq + p * 8;
                As[buf][m4 + 0][k] = f2tf(ra[p * 4 + 0]);
                As[buf][m4 + 1][k] = f2tf(ra[p * 4 + 1]);
                As[buf][m4 + 2][k] = f2tf(ra[p * 4 + 2]);
                As[buf][m4 + 3][k] = f2tf(ra[p * 4 + 3]);
            }
        }
        if (!TB) {
            int kb = tid >> 4;
            int nq = (tid & 15) * 4;
            uint4 t4;
            t4.x = f2tf(rb[0]); t4.y = f2tf(rb[1]);
            t4.z = f2tf(rb[2]); t4.w = f2tf(rb[3]);
            *reinterpret_cast<uint4*>(&Bs[buf][kb][nq]) = t4;
        } else {
            int nq = tid >> 2;
            int kb = (tid & 3) * 4;
            Bs[buf][kb + 0][nq] = f2tf(rb[0]);
            Bs[buf][kb + 1][nq] = f2tf(rb[1]);
            Bs[buf][kb + 2][nq] = f2tf(rb[2]);
            Bs[buf][kb + 3][nq] = f2tf(rb[3]);
        }
    };

    // ---------- prologue ----------
    load_regs(0);
    store_smem(0);
    __syncthreads();

    // ---------- main loop ----------
    for (int kt = 0; kt < nkt; kt++) {
        int cur = kt & 1;
        if (kt + 1 < nkt) load_regs(kt + 1);   // LDGs in flight during compute

        #pragma unroll
        for (int kk = 0; kk < GBK; kk += 8) {
            uint32_t b0[4], b1[4];
            #pragma unroll
            for (int nt = 0; nt < 4; nt++) {
                b0[nt] = Bs[cur][kk + tig][nw + nt * 8 + gid];
                b1[nt] = Bs[cur][kk + tig + 4][nw + nt * 8 + gid];
            }
            #pragma unroll
            for (int mt = 0; mt < 2; mt++) {
                int mb = mw + mt * 16;
                uint32_t a0 = As[cur][mb + gid][kk + tig];
                uint32_t a1 = As[cur][mb + gid + 8][kk + tig];
                uint32_t a2 = As[cur][mb + gid][kk + tig + 4];
                uint32_t a3 = As[cur][mb + gid + 8][kk + tig + 4];
                #pragma unroll
                for (int nt = 0; nt < 4; nt++)
                    mma_tf32(acc[mt][nt], a0, a1, a2, a3, b0[nt], b1[nt]);
            }
        }

        if (kt + 1 < nkt) store_smem((kt + 1) & 1);
        __syncthreads();
    }

    // ---------- epilogue ----------
    #pragma unroll
    for (int mt = 0; mt < 2; mt++) {
        int gm0 = bm + mw + mt * 16 + gid;
        int gm1 = gm0 + 8;
        float rs0 = 1.f, rs1 = 1.f;
        if (rowscale) {
            if (gm0 < M) rs0 = rowscale[gm0];
            if (gm1 < M) rs1 = rowscale[gm1];
        }
        #pragma unroll
        for (int nt = 0; nt < 4; nt++) {
            int gn0 = bn + nw + nt * 8 + 2 * tig;
            int gn1 = gn0 + 1;
            float v;
            if (gm0 < M) {
                if (gn0 < N) {
                    v = acc[mt][nt][0] * rs0;
                    if (EPI == 1) v = fmaxf(v, 0.f);
                    else if (EPI == 2) v = 1.f / (1.f + __expf(-v));
                    C[(size_t)gm0 * ldc + gn0] = v;
                }
                if (gn1 < N) {
                    v = acc[mt][nt][1] * rs0;
                    if (EPI == 1) v = fmaxf(v, 0.f);
                    else if (EPI == 2) v = 1.f / (1.f + __expf(-v));
                    C[(size_t)gm0 * ldc + gn1] = v;
                }
            }
            if (gm1 < M) {
                if (gn0 < N) {
                    v = acc[mt][nt][2] * rs1;
                    if (EPI == 1) v = fmaxf(v, 0.f);
                    else if (EPI == 2) v = 1.f / (1.f + __expf(-v));
                    C[(size_t)gm1 * ldc + gn0] = v;
                }
                if (gn1 < N) {
                    v = acc[mt][nt][3] * rs1;
                    if (EPI == 1) v = fmaxf(v, 0.f);
                    else if (EPI == 2) v = 1.f / (1.f + __expf(-v));
                    C[(size_t)gm1 * ldc + gn1] = v;
                }
            }
        }
    }
}

static inline dim3 gemm_grid(int M, int N) {
    return dim3((N + GBN - 1) / GBN, (M + GBM - 1) / GBM);
}

// ---------------- host orchestration ----------------
extern "C" void kernel_launch(void* const* d_in, const int* in_sizes, int n_in,
                              void* d_out, int out_size) {
    const float* R    = (const float*)d_in[0];
    const float* Dm   = (const float*)d_in[1];
    const float* Tm   = (const float*)d_in[2];
    const float* H_d  = (const float*)d_in[3];
    const float* H_t  = (const float*)d_in[4];
    const float* W1g[2] = {(const float*)d_in[5], (const float*)d_in[7]};
    const float* W2g[2] = {(const float*)d_in[6], (const float*)d_in[8]};
    const float* Wd[2]  = {(const float*)d_in[9], (const float*)d_in[11]};
    const float* Wt[2]  = {(const float*)d_in[10], (const float*)d_in[12]};
    const float* WdO  = (const float*)d_in[13];
    const float* WtO  = (const float*)d_in[14];
    float* out = (float*)d_out;

    float *S, *catd, *catt, *hdb, *htb, *hdp, *htp, *sd, *st, *nd, *nt, *ntraw, *part, *selval;
    int* selidx;
    cudaGetSymbolAddress((void**)&S,     g_S);
    cudaGetSymbolAddress((void**)&catd,  g_catd);
    cudaGetSymbolAddress((void**)&catt,  g_catt);
    cudaGetSymbolAddress((void**)&hdb,   g_hd);
    cudaGetSymbolAddress((void**)&htb,   g_ht);
    cudaGetSymbolAddress((void**)&hdp,   g_hdp);
    cudaGetSymbolAddress((void**)&htp,   g_htp);
    cudaGetSymbolAddress((void**)&sd,    g_sd);
    cudaGetSymbolAddress((void**)&st,    g_st);
    cudaGetSymbolAddress((void**)&nd,    g_nd);
    cudaGetSymbolAddress((void**)&nt,    g_nt);
    cudaGetSymbolAddress((void**)&ntraw, g_ntraw);
    cudaGetSymbolAddress((void**)&part,  g_part);
    cudaGetSymbolAddress((void**)&selidx, g_selidx);
    cudaGetSymbolAddress((void**)&selval, g_selval);

    rowsum_rsqrt<<<D_NUM, 256>>>(Dm, D_NUM, D_NUM, sd);
    rowsum_rsqrt<<<T_NUM, 256>>>(Tm, T_NUM, T_NUM, st);

    const float* hd = H_d;
    const float* ht = H_t;
    int F = FEAT;

    for (int lvl = 0; lvl < 2; lvl++) {
        // --- GL layer ---
        mma_gemm<false, false, 0><<<gemm_grid(D_NUM, UNITS), 256>>>(
            hd, W1g[lvl], hdp, D_NUM, UNITS, F, F, UNITS, UNITS, nullptr, nullptr);
        mma_gemm<false, false, 0><<<gemm_grid(T_NUM, UNITS), 256>>>(
            ht, W2g[lvl], htp, T_NUM, UNITS, F, F, UNITS, UNITS, nullptr, nullptr);
        mma_gemm<false, true, 2><<<gemm_grid(D_NUM, T_NUM), 256>>>(
            hdp, htp, S, D_NUM, T_NUM, UNITS, UNITS, UNITS, T_NUM, nullptr, nullptr);

        zero_vec<<<(T_NUM + 255) / 256, 256>>>(ntraw, T_NUM);
        topk_kernel<<<D_NUM, 256>>>(S, selidx, selval, nd, ntraw);
        nt_finish<<<(T_NUM + 255) / 256, 256>>>(ntraw, nt, T_NUM);

        // --- CGC layer on sparse learned graph ---
        gather_dt<<<D_NUM, 256>>>(selidx, selval, nd, nt, ht, F, catd + F, 3 * F);
        zero_strided<<<dim3((F + 255) / 256, T_NUM), 256>>>(catt + F, 3 * F, T_NUM, F);
        scatter_td<<<D_NUM * TOPK, 256>>>(selidx, selval, nd, nt, hd, F, catt + F, 3 * F);
        relu_strided<<<dim3((F + 255) / 256, T_NUM), 256>>>(catt + F, 3 * F, T_NUM, F);
        mma_gemm<false, false, 1><<<gemm_grid(D_NUM, F), 256>>>(
            Dm, hd, catd + 2 * F, D_NUM, F, D_NUM, D_NUM, F, 3 * F, sd, sd);
        mma_gemm<false, false, 1><<<gemm_grid(T_NUM, F), 256>>>(
            Tm, ht, catt + 2 * F, T_NUM, F, T_NUM, T_NUM, F, 3 * F, st, st);
        copy_strided<<<dim3((F + 255) / 256, D_NUM), 256>>>(catd, 3 * F, hd, F, D_NUM, F);
        copy_strided<<<dim3((F + 255) / 256, T_NUM), 256>>>(catt, 3 * F, ht, F, T_NUM, F);
        mma_gemm<false, false, 1><<<gemm_grid(D_NUM, UNITS), 256>>>(
            catd, Wd[lvl], hdb, D_NUM, UNITS, 3 * F, 3 * F, UNITS, UNITS, nullptr, nullptr);
        mma_gemm<false, false, 1><<<gemm_grid(T_NUM, UNITS), 256>>>(
            catt, Wt[lvl], htb, T_NUM, UNITS, 3 * F, 3 * F, UNITS, UNITS, nullptr, nullptr);
        hd = hdb; ht = htb; F = UNITS;
    }

    // --- output CGC on original (dense) R ---
    rowsum_rsqrt<<<D_NUM, 256>>>(R, D_NUM, T_NUM, nd);
    colsum_partial<<<dim3((T_NUM + 255) / 256, NCHUNK), 256>>>(R, D_NUM, T_NUM, part);
    colsum_finish<<<(T_NUM + 255) / 256, 256>>>(part, T_NUM, nt);

    mma_gemm<false, false, 1><<<gemm_grid(D_NUM, F), 256>>>(
        R, ht, catd + F, D_NUM, F, T_NUM, T_NUM, F, 3 * F, nd, nt);
    mma_gemm<true, false, 1><<<gemm_grid(T_NUM, F), 256>>>(
        R, hd, catt + F, T_NUM, F, D_NUM, T_NUM, F, 3 * F, nt, nd);
    mma_gemm<false, false, 1><<<gemm_grid(D_NUM, F), 256>>>(
        Dm, hd, catd + 2 * F, D_NUM, F, D_NUM, D_NUM, F, 3 * F, sd, sd);
    mma_gemm<false, false, 1><<<gemm_grid(T_NUM, F), 256>>>(
        Tm, ht, catt + 2 * F, T_NUM, F, T_NUM, T_NUM, F, 3 * F, st, st);
    copy_strided<<<dim3((F + 255) / 256, D_NUM), 256>>>(catd, 3 * F, hd, F, D_NUM, F);
    copy_strided<<<dim3((F + 255) / 256, T_NUM), 256>>>(catt, 3 * F, ht, F, T_NUM, F);

    mma_gemm<false, false, 1><<<gemm_grid(D_NUM, UNITS), 256>>>(
        catd, WdO, hdp, D_NUM, UNITS, 3 * F, 3 * F, UNITS, UNITS, nullptr, nullptr);
    mma_gemm<false, false, 1><<<gemm_grid(T_NUM, UNITS), 256>>>(
        catt, WtO, htp, T_NUM, UNITS, 3 * F, 3 * F, UNITS, UNITS, nullptr, nullptr);

    mma_gemm<false, true, 2><<<gemm_grid(D_NUM, T_NUM), 256>>>(
        hdp, htp, out, D_NUM, T_NUM, UNITS, UNITS, UNITS, T_NUM, nullptr, nullptr);
}

// round 5
// speedup vs baseline: 1.0870x; 1.0870x over previous
#include <cuda_runtime.h>
#include <math.h>
#include <stdint.h>

#define D_NUM 4000
#define T_NUM 2000
#define FEAT  256
#define UNITS 200
#define TOPK  10
#define NCHUNK 16

// ---------------- scratch (device globals; no runtime allocation) ----------------
__device__ float g_S[(size_t)D_NUM * T_NUM];
__device__ float g_catd[(size_t)D_NUM * 3 * FEAT];
__device__ float g_catt[(size_t)T_NUM * 3 * FEAT];
__device__ float g_hd[(size_t)D_NUM * FEAT];
__device__ float g_ht[(size_t)T_NUM * FEAT];
__device__ float g_hdp[(size_t)D_NUM * UNITS];
__device__ float g_htp[(size_t)T_NUM * UNITS];
__device__ float g_sd[D_NUM];
__device__ float g_st[T_NUM];
__device__ float g_nd[D_NUM];
__device__ float g_nt[T_NUM];
__device__ float g_ntraw[T_NUM];
__device__ float g_part[NCHUNK * T_NUM];
__device__ int   g_selidx[D_NUM * TOPK];
__device__ float g_selval[D_NUM * TOPK];

// ---------------- reductions ----------------
__global__ void rowsum_rsqrt(const float* __restrict__ A, int rows, int cols,
                             float* __restrict__ out) {
    int row = blockIdx.x;
    if (row >= rows) return;
    const float* a = A + (size_t)row * cols;
    float s = 0.f;
    for (int j = threadIdx.x; j < cols; j += blockDim.x) s += a[j];
    __shared__ float red[256];
    red[threadIdx.x] = s;
    __syncthreads();
    for (int off = 128; off > 0; off >>= 1) {
        if (threadIdx.x < off) red[threadIdx.x] += red[threadIdx.x + off];
        __syncthreads();
    }
    if (threadIdx.x == 0) {
        float n = red[0];
        if (n == 0.f) n = 1.f;
        out[row] = rsqrtf(n);
    }
}

__global__ void colsum_partial(const float* __restrict__ A, int rows, int cols,
                               float* __restrict__ part) {
    int j = blockIdx.x * blockDim.x + threadIdx.x;
    if (j >= cols) return;
    int chunk = (rows + NCHUNK - 1) / NCHUNK;
    int r0 = blockIdx.y * chunk;
    int r1 = r0 + chunk; if (r1 > rows) r1 = rows;
    float s = 0.f;
    for (int i = r0; i < r1; i++) s += A[(size_t)i * cols + j];
    part[blockIdx.y * cols + j] = s;
}

__global__ void colsum_finish(const float* __restrict__ part, int cols,
                              float* __restrict__ out) {
    int j = blockIdx.x * blockDim.x + threadIdx.x;
    if (j >= cols) return;
    float s = 0.f;
    for (int c = 0; c < NCHUNK; c++) s += part[c * cols + j];
    if (s == 0.f) s = 1.f;
    out[j] = rsqrtf(s);
}

// ---------------- small utility kernels ----------------
__global__ void zero_vec(float* __restrict__ p, int n) {
    int i = blockIdx.x * blockDim.x + threadIdx.x;
    if (i < n) p[i] = 0.f;
}

__global__ void zero_strided(float* __restrict__ dst, int ld, int rows, int cols) {
    int c = blockIdx.x * blockDim.x + threadIdx.x;
    int r = blockIdx.y;
    if (c < cols && r < rows) dst[(size_t)r * ld + c] = 0.f;
}

__global__ void relu_strided(float* __restrict__ dst, int ld, int rows, int cols) {
    int c = blockIdx.x * blockDim.x + threadIdx.x;
    int r = blockIdx.y;
    if (c < cols && r < rows) {
        size_t o = (size_t)r * ld + c;
        dst[o] = fmaxf(dst[o], 0.f);
    }
}

__global__ void copy_strided(float* __restrict__ dst, int ldd,
                             const float* __restrict__ src, int lds,
                             int rows, int cols) {
    int c = blockIdx.x * blockDim.x + threadIdx.x;
    int r = blockIdx.y;
    if (c < cols && r < rows)
        dst[(size_t)r * ldd + c] = src[(size_t)r * lds + c];
}

// ---------------- top-k (exact stable-sort tie semantics: min index wins) -------
__global__ void topk_kernel(const float* __restrict__ S,
                            int* __restrict__ selidx, float* __restrict__ selval,
                            float* __restrict__ nd_out, float* __restrict__ ntraw) {
    __shared__ float sv[T_NUM];
    __shared__ float rv[256];
    __shared__ int   ri[256];
    __shared__ int   sel[TOPK];
    __shared__ float selv[TOPK];
    int row = blockIdx.x;
    const float* srow = S + (size_t)row * T_NUM;
    for (int j = threadIdx.x; j < T_NUM; j += 256) sv[j] = srow[j];
    __syncthreads();
    for (int it = 0; it < TOPK; it++) {
        float best = -3.f; int bidx = T_NUM;
        for (int j = threadIdx.x; j < T_NUM; j += 256) {
            float v = sv[j];
            if (v > best || (v == best && j < bidx)) { best = v; bidx = j; }
        }
        rv[threadIdx.x] = best; ri[threadIdx.x] = bidx;
        __syncthreads();
        for (int off = 128; off > 0; off >>= 1) {
            if (threadIdx.x < off) {
                float v2 = rv[threadIdx.x + off]; int i2 = ri[threadIdx.x + off];
                if (v2 > rv[threadIdx.x] ||
                    (v2 == rv[threadIdx.x] && i2 < ri[threadIdx.x])) {
                    rv[threadIdx.x] = v2; ri[threadIdx.x] = i2;
                }
            }
            __syncthreads();
        }
        if (threadIdx.x == 0) {
            sel[it] = ri[0]; selv[it] = rv[0];
            sv[ri[0]] = -2.f;
        }
        __syncthreads();
    }
    if (threadIdx.x < TOPK) {
        selidx[row * TOPK + threadIdx.x] = sel[threadIdx.x];
        selval[row * TOPK + threadIdx.x] = selv[threadIdx.x];
        atomicAdd(&ntraw[sel[threadIdx.x]], selv[threadIdx.x]);
    }
    if (threadIdx.x == 0) {
        float s = 0.f;
        #pragma unroll
        for (int t = 0; t < TOPK; t++) s += selv[t];
        if (s == 0.f) s = 1.f;
        nd_out[row] = rsqrtf(s);
    }
}

__global__ void nt_finish(const float* __restrict__ raw, float* __restrict__ out, int n) {
    int i = blockIdx.x * blockDim.x + threadIdx.x;
    if (i < n) {
        float s = raw[i];
        if (s == 0.f) s = 1.f;
        out[i] = rsqrtf(s);
    }
}

// ---------------- sparse CGC kernels ----------------
__global__ void gather_dt(const int* __restrict__ selidx, const float* __restrict__ selval,
                          const float* __restrict__ nd, const float* __restrict__ nt,
                          const float* __restrict__ ht, int F,
                          float* __restrict__ outd, int ldo) {
    int d = blockIdx.x;
    __shared__ int   ci[TOPK];
    __shared__ float cw[TOPK];
    if (threadIdx.x < TOPK) {
        int c = selidx[d * TOPK + threadIdx.x];
        ci[threadIdx.x] = c;
        cw[threadIdx.x] = selval[d * TOPK + threadIdx.x] * nt[c];
    }
    __syncthreads();
    float ndv = nd[d];
    for (int f = threadIdx.x; f < F; f += blockDim.x) {
        float s = 0.f;
        #pragma unroll
        for (int j = 0; j < TOPK; j++) s += cw[j] * ht[(size_t)ci[j] * F + f];
        outd[(size_t)d * ldo + f] = fmaxf(s * ndv, 0.f);
    }
}

__global__ void scatter_td(const int* __restrict__ selidx, const float* __restrict__ selval,
                           const float* __restrict__ nd, const float* __restrict__ nt,
                           const float* __restrict__ hd, int F,
                           float* __restrict__ outt, int ldo) {
    int e = blockIdx.x;
    int d = e / TOPK;
    int t = selidx[e];
    float w = selval[e] * nd[d] * nt[t];
    const float* src = hd + (size_t)d * F;
    float* dst = outt + (size_t)t * ldo;
    for (int f = threadIdx.x; f < F; f += blockDim.x)
        atomicAdd(&dst[f], w * src[f]);
}

// ---------------- TF32 tensor-core GEMM, 64x64 CTA for high residency ----------
// C = EPI( rowscale[m] * sum_k ( A(m,k)*kscale[k] ) * B(k,n) )
// TA: A stored [K,M].  TB: B stored [N,K].  EPI: 0 none, 1 relu, 2 sigmoid.
// 128 threads, 4 warps (2x2), warp tile 32x32, double-buffered GBK=16.

__device__ __forceinline__ uint32_t f2tf(float x) {
    uint32_t r;
    asm("cvt.rna.tf32.f32 %0, %1;" : "=r"(r) : "f"(x));
    return r;
}

__device__ __forceinline__ void mma_tf32(float c[4], uint32_t a0, uint32_t a1,
                                         uint32_t a2, uint32_t a3,
                                         uint32_t b0, uint32_t b1) {
    asm volatile(
        "mma.sync.aligned.m16n8k8.row.col.f32.tf32.tf32.f32 "
        "{%0,%1,%2,%3}, {%4,%5,%6,%7}, {%8,%9}, {%0,%1,%2,%3};"
        : "+f"(c[0]), "+f"(c[1]), "+f"(c[2]), "+f"(c[3])
        : "r"(a0), "r"(a1), "r"(a2), "r"(a3), "r"(b0), "r"(b1));
}

#define GBM 64
#define GBN 64
#define GBK 16
#define GTHREADS 128
#define ASTR (GBK + 4)   // 20
#define BSTR (GBN + 8)   // 72

template <bool TA, bool TB, int EPI>
__global__ __launch_bounds__(GTHREADS)
void mma_gemm(const float* __restrict__ A, const float* __restrict__ B,
              float* __restrict__ C,
              int M, int N, int K, int lda, int ldb, int ldc,
              const float* __restrict__ rowscale,
              const float* __restrict__ kscale) {
    __shared__ uint32_t As[2][GBM][ASTR];
    __shared__ uint32_t Bs[2][GBK][BSTR];

    int tid = threadIdx.x;
    int lane = tid & 31;
    int warp = tid >> 5;                // 0..3
    int gid = lane >> 2, tig = lane & 3;
    int mw = (warp & 1) * 32;
    int nw = (warp >> 1) * 32;
    int bm = blockIdx.y * GBM;
    int bn = blockIdx.x * GBN;

    float acc[2][4][4];
    #pragma unroll
    for (int i = 0; i < 2; i++)
        #pragma unroll
        for (int j = 0; j < 4; j++)
            #pragma unroll
            for (int l = 0; l < 4; l++) acc[i][j][l] = 0.f;

    float ra[8];
    float rb[8];

    int nkt = (K + GBK - 1) / GBK;

    // ---------- staging helpers ----------
    auto load_regs = [&](int kt) {
        int k0 = kt * GBK;
        if (!TA) {
            // 64 rows x 16 k / 128 thr = 8 contiguous k per thread
            int m0 = tid >> 1;
            int kq = (tid & 1) * 8;
            int gm = bm + m0;
            #pragma unroll
            for (int p = 0; p < 2; p++) {
                int gk = k0 + kq + p * 4;
                float4 v = make_float4(0.f, 0.f, 0.f, 0.f);
                if (gm < M && gk < K)
                    v = *reinterpret_cast<const float4*>(&A[(size_t)gm * lda + gk]);
                if (kscale && gk < K) {
                    v.x *= kscale[gk];     v.y *= kscale[gk + 1];
                    v.z *= kscale[gk + 2]; v.w *= kscale[gk + 3];
                }
                ra[p * 4 + 0] = v.x; ra[p * 4 + 1] = v.y;
                ra[p * 4 + 2] = v.z; ra[p * 4 + 3] = v.w;
            }
        } else {
            // A stored [K,M]: k = tid>>4 (+8 for p), m4 = (tid&15)*4
            int kq = tid >> 4;          // 0..7
            int m4 = (tid & 15) * 4;
            int gm = bm + m4;
            #pragma unroll
            for (int p = 0; p < 2; p++) {
                int gk = k0 + kq + p * 8;
                float4 v = make_float4(0.f, 0.f, 0.f, 0.f);
                if (gk < K && gm < M)
                    v = *reinterpret_cast<const float4*>(&A[(size_t)gk * lda + gm]);
                if (kscale && gk < K) {
                    float ks = kscale[gk];
                    v.x *= ks; v.y *= ks; v.z *= ks; v.w *= ks;
                }
                ra[p * 4 + 0] = v.x; ra[p * 4 + 1] = v.y;
                ra[p * 4 + 2] = v.z; ra[p * 4 + 3] = v.w;
            }
        }
        if (!TB) {
            // 16 k x 64 n / 128 thr = 8 contiguous n per thread
            int kb = tid >> 3;          // 0..15
            int nq = (tid & 7) * 8;
            int gk = k0 + kb;
            #pragma unroll
            for (int p = 0; p < 2; p++) {
                int gn = bn + nq + p * 4;
                float4 v = make_float4(0.f, 0.f, 0.f, 0.f);
                if (gk < K && gn < N)
                    v = *reinterpret_cast<const float4*>(&B[(size_t)gk * ldb + gn]);
                rb[p * 4 + 0] = v.x; rb[p * 4 + 1] = v.y;
                rb[p * 4 + 2] = v.z; rb[p * 4 + 3] = v.w;
            }
        } else {
            // B stored [N,K]: n = tid>>1, 8 contiguous k per thread
            int nq = tid >> 1;          // 0..63
            int kq = (tid & 1) * 8;
            int gn = bn + nq;
            #pragma unroll
            for (int p = 0; p < 2; p++) {
                int gk = k0 + kq + p * 4;
                float4 v = make_float4(0.f, 0.f, 0.f, 0.f);
                if (gn < N && gk < K)
                    v = *reinterpret_cast<const float4*>(&B[(size_t)gn * ldb + gk]);
                rb[p * 4 + 0] = v.x; rb[p * 4 + 1] = v.y;
                rb[p * 4 + 2] = v.z; rb[p * 4 + 3] = v.w;
            }
        }
    };

    auto store_smem = [&](int buf) {
        if (!TA) {
            int m0 = tid >> 1;
            int kq = (tid & 1) * 8;
            #pragma unroll
            for (int p = 0; p < 2; p++) {
                uint4 t4;
                t4.x = f2tf(ra[p * 4 + 0]); t4.y = f2tf(ra[p * 4 + 1]);
                t4.z = f2tf(ra[p * 4 + 2]); t4.w = f2tf(ra[p * 4 + 3]);
                *reinterpret_cast<uint4*>(&As[buf][m0][kq + p * 4]) = t4;
            }
        } else {
            int kq = tid >> 4;
            int m4 = (tid & 15) * 4;
            #pragma unroll
            for (int p = 0; p < 2; p++) {
                int k = kq + p * 8;
                As[buf][m4 + 0][k] = f2tf(ra[p * 4 + 0]);
                As[buf][m4 + 1][k] = f2tf(ra[p * 4 + 1]);
                As[buf][m4 + 2][k] = f2tf(ra[p * 4 + 2]);
                As[buf][m4 + 3][k] = f2tf(ra[p * 4 + 3]);
            }
        }
        if (!TB) {
            int kb = tid >> 3;
            int nq = (tid & 7) * 8;
            #pragma unroll
            for (int p = 0; p < 2; p++) {
                uint4 t4;
                t4.x = f2tf(rb[p * 4 + 0]); t4.y = f2tf(rb[p * 4 + 1]);
                t4.z = f2tf(rb[p * 4 + 2]); t4.w = f2tf(rb[p * 4 + 3]);
                *reinterpret_cast<uint4*>(&Bs[buf][kb][nq + p * 4]) = t4;
            }
        } else {
            int nq = tid >> 1;
            int kq = (tid & 1) * 8;
            #pragma unroll
            for (int p = 0; p < 2; p++) {
                int k = kq + p * 4;
                Bs[buf][k + 0][nq] = f2tf(rb[p * 4 + 0]);
                Bs[buf][k + 1][nq] = f2tf(rb[p * 4 + 1]);
                Bs[buf][k + 2][nq] = f2tf(rb[p * 4 + 2]);
                Bs[buf][k + 3][nq] = f2tf(rb[p * 4 + 3]);
            }
        }
    };

    // ---------- prologue ----------
    load_regs(0);
    store_smem(0);
    __syncthreads();

    // ---------- main loop ----------
    for (int kt = 0; kt < nkt; kt++) {
        int cur = kt & 1;
        if (kt + 1 < nkt) load_regs(kt + 1);

        #pragma unroll
        for (int kk = 0; kk < GBK; kk += 8) {
            uint32_t b0[4], b1[4];
            #pragma unroll
            for (int nt = 0; nt < 4; nt++) {
                b0[nt] = Bs[cur][kk + tig][nw + nt * 8 + gid];
                b1[nt] = Bs[cur][kk + tig + 4][nw + nt * 8 + gid];
            }
            #pragma unroll
            for (int mt = 0; mt < 2; mt++) {
                int mb = mw + mt * 16;
                uint32_t a0 = As[cur][mb + gid][kk + tig];
                uint32_t a1 = As[cur][mb + gid + 8][kk + tig];
                uint32_t a2 = As[cur][mb + gid][kk + tig + 4];
                uint32_t a3 = As[cur][mb + gid + 8][kk + tig + 4];
                #pragma unroll
                for (int nt = 0; nt < 4; nt++)
                    mma_tf32(acc[mt][nt], a0, a1, a2, a3, b0[nt], b1[nt]);
            }
        }

        if (kt + 1 < nkt) store_smem((kt + 1) & 1);
        __syncthreads();
    }

    // ---------- epilogue ----------
    #pragma unroll
    for (int mt = 0; mt < 2; mt++) {
        int gm0 = bm + mw + mt * 16 + gid;
        int gm1 = gm0 + 8;
        float rs0 = 1.f, rs1 = 1.f;
        if (rowscale) {
            if (gm0 < M) rs0 = rowscale[gm0];
            if (gm1 < M) rs1 = rowscale[gm1];
        }
        #pragma unroll
        for (int nt = 0; nt < 4; nt++) {
            int gn0 = bn + nw + nt * 8 + 2 * tig;
            int gn1 = gn0 + 1;
            float v;
            if (gm0 < M) {
                if (gn0 < N) {
                    v = acc[mt][nt][0] * rs0;
                    if (EPI == 1) v = fmaxf(v, 0.f);
                    else if (EPI == 2) v = 1.f / (1.f + __expf(-v));
                    C[(size_t)gm0 * ldc + gn0] = v;
                }
                if (gn1 < N) {
                    v = acc[mt][nt][1] * rs0;
                    if (EPI == 1) v = fmaxf(v, 0.f);
                    else if (EPI == 2) v = 1.f / (1.f + __expf(-v));
                    C[(size_t)gm0 * ldc + gn1] = v;
                }
            }
            if (gm1 < M) {
                if (gn0 < N) {
                    v = acc[mt][nt][2] * rs1;
                    if (EPI == 1) v = fmaxf(v, 0.f);
                    else if (EPI == 2) v = 1.f / (1.f + __expf(-v));
                    C[(size_t)gm1 * ldc + gn0] = v;
                }
                if (gn1 < N) {
                    v = acc[mt][nt][3] * rs1;
                    if (EPI == 1) v = fmaxf(v, 0.f);
                    else if (EPI == 2) v = 1.f / (1.f + __expf(-v));
                    C[(size_t)gm1 * ldc + gn1] = v;
                }
            }
        }
    }
}

static inline dim3 gemm_grid(int M, int N) {
    return dim3((N + GBN - 1) / GBN, (M + GBM - 1) / GBM);
}

// ---------------- host orchestration ----------------
extern "C" void kernel_launch(void* const* d_in, const int* in_sizes, int n_in,
                              void* d_out, int out_size) {
    const float* R    = (const float*)d_in[0];
    const float* Dm   = (const float*)d_in[1];
    const float* Tm   = (const float*)d_in[2];
    const float* H_d  = (const float*)d_in[3];
    const float* H_t  = (const float*)d_in[4];
    const float* W1g[2] = {(const float*)d_in[5], (const float*)d_in[7]};
    const float* W2g[2] = {(const float*)d_in[6], (const float*)d_in[8]};
    const float* Wd[2]  = {(const float*)d_in[9], (const float*)d_in[11]};
    const float* Wt[2]  = {(const float*)d_in[10], (const float*)d_in[12]};
    const float* WdO  = (const float*)d_in[13];
    const float* WtO  = (const float*)d_in[14];
    float* out = (float*)d_out;

    float *S, *catd, *catt, *hdb, *htb, *hdp, *htp, *sd, *st, *nd, *nt, *ntraw, *part, *selval;
    int* selidx;
    cudaGetSymbolAddress((void**)&S,     g_S);
    cudaGetSymbolAddress((void**)&catd,  g_catd);
    cudaGetSymbolAddress((void**)&catt,  g_catt);
    cudaGetSymbolAddress((void**)&hdb,   g_hd);
    cudaGetSymbolAddress((void**)&htb,   g_ht);
    cudaGetSymbolAddress((void**)&hdp,   g_hdp);
    cudaGetSymbolAddress((void**)&htp,   g_htp);
    cudaGetSymbolAddress((void**)&sd,    g_sd);
    cudaGetSymbolAddress((void**)&st,    g_st);
    cudaGetSymbolAddress((void**)&nd,    g_nd);
    cudaGetSymbolAddress((void**)&nt,    g_nt);
    cudaGetSymbolAddress((void**)&ntraw, g_ntraw);
    cudaGetSymbolAddress((void**)&part,  g_part);
    cudaGetSymbolAddress((void**)&selidx, g_selidx);
    cudaGetSymbolAddress((void**)&selval, g_selval);

    rowsum_rsqrt<<<D_NUM, 256>>>(Dm, D_NUM, D_NUM, sd);
    rowsum_rsqrt<<<T_NUM, 256>>>(Tm, T_NUM, T_NUM, st);

    const float* hd = H_d;
    const float* ht = H_t;
    int F = FEAT;

    for (int lvl = 0; lvl < 2; lvl++) {
        // --- GL layer ---
        mma_gemm<false, false, 0><<<gemm_grid(D_NUM, UNITS), GTHREADS>>>(
            hd, W1g[lvl], hdp, D_NUM, UNITS, F, F, UNITS, UNITS, nullptr, nullptr);
        mma_gemm<false, false, 0><<<gemm_grid(T_NUM, UNITS), GTHREADS>>>(
            ht, W2g[lvl], htp, T_NUM, UNITS, F, F, UNITS, UNITS, nullptr, nullptr);
        mma_gemm<false, true, 2><<<gemm_grid(D_NUM, T_NUM), GTHREADS>>>(
            hdp, htp, S, D_NUM, T_NUM, UNITS, UNITS, UNITS, T_NUM, nullptr, nullptr);

        zero_vec<<<(T_NUM + 255) / 256, 256>>>(ntraw, T_NUM);
        topk_kernel<<<D_NUM, 256>>>(S, selidx, selval, nd, ntraw);
        nt_finish<<<(T_NUM + 255) / 256, 256>>>(ntraw, nt, T_NUM);

        // --- CGC layer on sparse learned graph ---
        gather_dt<<<D_NUM, 256>>>(selidx, selval, nd, nt, ht, F, catd + F, 3 * F);
        zero_strided<<<dim3((F + 255) / 256, T_NUM), 256>>>(catt + F, 3 * F, T_NUM, F);
        scatter_td<<<D_NUM * TOPK, 256>>>(selidx, selval, nd, nt, hd, F, catt + F, 3 * F);
        relu_strided<<<dim3((F + 255) / 256, T_NUM), 256>>>(catt + F, 3 * F, T_NUM, F);
        mma_gemm<false, false, 1><<<gemm_grid(D_NUM, F), GTHREADS>>>(
            Dm, hd, catd + 2 * F, D_NUM, F, D_NUM, D_NUM, F, 3 * F, sd, sd);
        mma_gemm<false, false, 1><<<gemm_grid(T_NUM, F), GTHREADS>>>(
            Tm, ht, catt + 2 * F, T_NUM, F, T_NUM, T_NUM, F, 3 * F, st, st);
        copy_strided<<<dim3((F + 255) / 256, D_NUM), 256>>>(catd, 3 * F, hd, F, D_NUM, F);
        copy_strided<<<dim3((F + 255) / 256, T_NUM), 256>>>(catt, 3 * F, ht, F, T_NUM, F);
        mma_gemm<false, false, 1><<<gemm_grid(D_NUM, UNITS), GTHREADS>>>(
            catd, Wd[lvl], hdb, D_NUM, UNITS, 3 * F, 3 * F, UNITS, UNITS, nullptr, nullptr);
        mma_gemm<false, false, 1><<<gemm_grid(T_NUM, UNITS), GTHREADS>>>(
            catt, Wt[lvl], htb, T_NUM, UNITS, 3 * F, 3 * F, UNITS, UNITS, nullptr, nullptr);
        hd = hdb; ht = htb; F = UNITS;
    }

    // --- output CGC on original (dense) R ---
    rowsum_rsqrt<<<D_NUM, 256>>>(R, D_NUM, T_NUM, nd);
    colsum_partial<<<dim3((T_NUM + 255) / 256, NCHUNK), 256>>>(R, D_NUM, T_NUM, part);
    colsum_finish<<<(T_NUM + 255) / 256, 256>>>(part, T_NUM, nt);

    mma_gemm<false, false, 1><<<gemm_grid(D_NUM, F), GTHREADS>>>(
        R, ht, catd + F, D_NUM, F, T_NUM, T_NUM, F, 3 * F, nd, nt);
    mma_gemm<true, false, 1><<<gemm_grid(T_NUM, F), GTHREADS>>>(
        R, hd, catt + F, T_NUM, F, D_NUM, T_NUM, F, 3 * F, nt, nd);
    mma_gemm<false, false, 1><<<gemm_grid(D_NUM, F), GTHREADS>>>(
        Dm, hd, catd + 2 * F, D_NUM, F, D_NUM, D_NUM, F, 3 * F, sd, sd);
    mma_gemm<false, false, 1><<<gemm_grid(T_NUM, F), GTHREADS>>>(
        Tm, ht, catt + 2 * F, T_NUM, F, T_NUM, T_NUM, F, 3 * F, st, st);
    copy_strided<<<dim3((F + 255) / 256, D_NUM), 256>>>(catd, 3 * F, hd, F, D_NUM, F);
    copy_strided<<<dim3((F + 255) / 256, T_NUM), 256>>>(catt, 3 * F, ht, F, T_NUM, F);

    mma_gemm<false, false, 1><<<gemm_grid(D_NUM, UNITS), GTHREADS>>>(
        catd, WdO, hdp, D_NUM, UNITS, 3 * F, 3 * F, UNITS, UNITS, nullptr, nullptr);
    mma_gemm<false, false, 1><<<gemm_grid(T_NUM, UNITS), GTHREADS>>>(
        catt, WtO, htp, T_NUM, UNITS, 3 * F, 3 * F, UNITS, UNITS, nullptr, nullptr);

    mma_gemm<false, true, 2><<<gemm_grid(D_NUM, T_NUM), GTHREADS>>>(
        hdp, htp, out, D_NUM, T_NUM, UNITS, UNITS, UNITS, T_NUM, nullptr, nullptr);
}

// round 6
// speedup vs baseline: 1.3738x; 1.2638x over previous
#include <cuda_runtime.h>
#include <math.h>
#include <stdint.h>

#define D_NUM 4000
#define T_NUM 2000
#define FEAT  256
#define UNITS 200
#define TOPK  10
#define NCHUNK 16

// ---------------- scratch (device globals; no runtime allocation) ----------------
__device__ float g_S[(size_t)D_NUM * T_NUM];
__device__ float g_catd[(size_t)D_NUM * 3 * FEAT];
__device__ float g_catt[(size_t)T_NUM * 3 * FEAT];
__device__ float g_hd[(size_t)D_NUM * FEAT];
__device__ float g_ht[(size_t)T_NUM * FEAT];
__device__ float g_hdp[(size_t)D_NUM * UNITS];
__device__ float g_htp[(size_t)T_NUM * UNITS];
__device__ float g_bsd[(size_t)D_NUM * FEAT];   // prescaled+rounded B buffer 1
__device__ float g_bst[(size_t)D_NUM * FEAT];   // prescaled+rounded B buffer 2
__device__ float g_sd[D_NUM];
__device__ float g_st[T_NUM];
__device__ float g_nd[D_NUM];
__device__ float g_nt[T_NUM];
__device__ float g_ntraw[T_NUM];
__device__ float g_part[NCHUNK * T_NUM];
__device__ int   g_selidx[D_NUM * TOPK];
__device__ float g_selval[D_NUM * TOPK];

__device__ __forceinline__ uint32_t f2tf(float x) {
    uint32_t r;
    asm("cvt.rna.tf32.f32 %0, %1;" : "=r"(r) : "f"(x));
    return r;
}
__device__ __forceinline__ float roundtf(float x) {
    return __uint_as_float(f2tf(x));
}

// ---------------- reductions ----------------
__global__ void rowsum_rsqrt(const float* __restrict__ A, int rows, int cols,
                             float* __restrict__ out) {
    int row = blockIdx.x;
    if (row >= rows) return;
    const float* a = A + (size_t)row * cols;
    float s = 0.f;
    for (int j = threadIdx.x; j < cols; j += blockDim.x) s += a[j];
    __shared__ float red[256];
    red[threadIdx.x] = s;
    __syncthreads();
    for (int off = 128; off > 0; off >>= 1) {
        if (threadIdx.x < off) red[threadIdx.x] += red[threadIdx.x + off];
        __syncthreads();
    }
    if (threadIdx.x == 0) {
        float n = red[0];
        if (n == 0.f) n = 1.f;
        out[row] = rsqrtf(n);
    }
}

__global__ void colsum_partial(const float* __restrict__ A, int rows, int cols,
                               float* __restrict__ part) {
    int j = blockIdx.x * blockDim.x + threadIdx.x;
    if (j >= cols) return;
    int chunk = (rows + NCHUNK - 1) / NCHUNK;
    int r0 = blockIdx.y * chunk;
    int r1 = r0 + chunk; if (r1 > rows) r1 = rows;
    float s = 0.f;
    for (int i = r0; i < r1; i++) s += A[(size_t)i * cols + j];
    part[blockIdx.y * cols + j] = s;
}

__global__ void colsum_finish(const float* __restrict__ part, int cols,
                              float* __restrict__ out) {
    int j = blockIdx.x * blockDim.x + threadIdx.x;
    if (j >= cols) return;
    float s = 0.f;
    for (int c = 0; c < NCHUNK; c++) s += part[c * cols + j];
    if (s == 0.f) s = 1.f;
    out[j] = rsqrtf(s);
}

// ---------------- prep / utility kernels ----------------
// dst[r,c] = tf32_round( scale[r] * src[r,c] )
__global__ void prescale_round(float* __restrict__ dst, const float* __restrict__ src,
                               const float* __restrict__ scale, int rows, int cols) {
    int c = blockIdx.x * blockDim.x + threadIdx.x;
    int r = blockIdx.y;
    if (c < cols && r < rows) {
        size_t o = (size_t)r * cols + c;
        dst[o] = roundtf(scale[r] * src[o]);
    }
}

__global__ void zero_vec(float* __restrict__ p, int n) {
    int i = blockIdx.x * blockDim.x + threadIdx.x;
    if (i < n) p[i] = 0.f;
}

__global__ void zero_strided(float* __restrict__ dst, int ld, int rows, int cols) {
    int c = blockIdx.x * blockDim.x + threadIdx.x;
    int r = blockIdx.y;
    if (c < cols && r < rows) dst[(size_t)r * ld + c] = 0.f;
}

__global__ void relu_round_strided(float* __restrict__ dst, int ld, int rows, int cols) {
    int c = blockIdx.x * blockDim.x + threadIdx.x;
    int r = blockIdx.y;
    if (c < cols && r < rows) {
        size_t o = (size_t)r * ld + c;
        dst[o] = roundtf(fmaxf(dst[o], 0.f));
    }
}

__global__ void copy_round_strided(float* __restrict__ dst, int ldd,
                                   const float* __restrict__ src, int lds,
                                   int rows, int cols) {
    int c = blockIdx.x * blockDim.x + threadIdx.x;
    int r = blockIdx.y;
    if (c < cols && r < rows)
        dst[(size_t)r * ldd + c] = roundtf(src[(size_t)r * lds + c]);
}

// ---------------- top-k (register candidates; min-index tie like stable argsort) -
__global__ void topk_kernel(const float* __restrict__ S,
                            int* __restrict__ selidx, float* __restrict__ selval,
                            float* __restrict__ nd_out, float* __restrict__ ntraw) {
    int row = blockIdx.x;
    int tid = threadIdx.x;
    int lane = tid & 31, wid = tid >> 5;
    const float* srow = S + (size_t)row * T_NUM;

    float v[8];
    #pragma unroll
    for (int i = 0; i < 8; i++) {
        int j = tid + i * 256;
        v[i] = (j < T_NUM) ? srow[j] : -3.f;
    }

    __shared__ float wv[8];
    __shared__ int   wi[8];
    __shared__ int   bidx_s;
    __shared__ int   sel[TOPK];
    __shared__ float selv[TOPK];

    for (int it = 0; it < TOPK; it++) {
        float best = v[0]; int bi = tid;
        #pragma unroll
        for (int i = 1; i < 8; i++) {
            int j = tid + i * 256;
            if (v[i] > best) { best = v[i]; bi = j; }   // ascending j: strict > keeps min idx
        }
        #pragma unroll
        for (int off = 16; off > 0; off >>= 1) {
            float ov = __shfl_xor_sync(0xffffffffu, best, off);
            int   oi = __shfl_xor_sync(0xffffffffu, bi, off);
            if (ov > best || (ov == best && oi < bi)) { best = ov; bi = oi; }
        }
        if (lane == 0) { wv[wid] = best; wi[wid] = bi; }
        __syncthreads();
        if (tid == 0) {
            float b = wv[0]; int x = wi[0];
            #pragma unroll
            for (int w = 1; w < 8; w++)
                if (wv[w] > b || (wv[w] == b && wi[w] < x)) { b = wv[w]; x = wi[w]; }
            bidx_s = x; sel[it] = x; selv[it] = b;
        }
        __syncthreads();
        int x = bidx_s;
        if ((x & 255) == tid) v[x >> 8] = -3.f;
    }

    if (tid < TOPK) {
        selidx[row * TOPK + tid] = sel[tid];
        selval[row * TOPK + tid] = selv[tid];
        atomicAdd(&ntraw[sel[tid]], selv[tid]);
    }
    if (tid == 0) {
        float s = 0.f;
        #pragma unroll
        for (int t = 0; t < TOPK; t++) s += selv[t];
        if (s == 0.f) s = 1.f;
        nd_out[row] = rsqrtf(s);
    }
}

// ---------------- sparse CGC kernels (nt normalization inlined) ----------------
__global__ void gather_dt(const int* __restrict__ selidx, const float* __restrict__ selval,
                          const float* __restrict__ nd, const float* __restrict__ ntraw,
                          const float* __restrict__ ht, int F,
                          float* __restrict__ outd, int ldo) {
    int d = blockIdx.x;
    __shared__ int   ci[TOPK];
    __shared__ float cw[TOPK];
    if (threadIdx.x < TOPK) {
        int c = selidx[d * TOPK + threadIdx.x];
        float s = ntraw[c];
        if (s == 0.f) s = 1.f;
        ci[threadIdx.x] = c;
        cw[threadIdx.x] = selval[d * TOPK + threadIdx.x] * rsqrtf(s);
    }
    __syncthreads();
    float ndv = nd[d];
    for (int f = threadIdx.x; f < F; f += blockDim.x) {
        float s = 0.f;
        #pragma unroll
        for (int j = 0; j < TOPK; j++) s += cw[j] * ht[(size_t)ci[j] * F + f];
        outd[(size_t)d * ldo + f] = roundtf(fmaxf(s * ndv, 0.f));
    }
}

__global__ void scatter_td(const int* __restrict__ selidx, const float* __restrict__ selval,
                           const float* __restrict__ nd, const float* __restrict__ ntraw,
                           const float* __restrict__ hd, int F,
                           float* __restrict__ outt, int ldo) {
    int e = blockIdx.x;
    int d = e / TOPK;
    int t = selidx[e];
    float s = ntraw[t];
    if (s == 0.f) s = 1.f;
    float w = selval[e] * nd[d] * rsqrtf(s);
    const float* src = hd + (size_t)d * F;
    float* dst = outt + (size_t)t * ldo;
    for (int f = threadIdx.x; f < F; f += blockDim.x)
        atomicAdd(&dst[f], w * src[f]);
}

// ---------------- TF32 tensor-core GEMM ----------------
// C = EPI( rowscale[m] * sum_k A(m,k)*B(k,n) )
// TA: A stored [K,M].  TB: B stored [N,K].
// EPI: 0 none, 1 relu, 2 sigmoid, 3 tf32-round, 4 relu+tf32-round.
// ACVT/BCVT: apply cvt.rna.tf32 on fragments (input is raw fp32) or not (pre-rounded).
// 128 threads, 4 warps (2x2), warp tile 32x32, double-buffered GBK=16.

__device__ __forceinline__ void mma_tf32(float c[4], uint32_t a0, uint32_t a1,
                                         uint32_t a2, uint32_t a3,
                                         uint32_t b0, uint32_t b1) {
    asm volatile(
        "mma.sync.aligned.m16n8k8.row.col.f32.tf32.tf32.f32 "
        "{%0,%1,%2,%3}, {%4,%5,%6,%7}, {%8,%9}, {%0,%1,%2,%3};"
        : "+f"(c[0]), "+f"(c[1]), "+f"(c[2]), "+f"(c[3])
        : "r"(a0), "r"(a1), "r"(a2), "r"(a3), "r"(b0), "r"(b1));
}

__device__ __forceinline__ uint32_t cvt_bits(uint32_t raw) {
    return f2tf(__uint_as_float(raw));
}

#define GBM 64
#define GBN 64
#define GBK 16
#define GTHREADS 128
#define ASTR (GBK + 4)   // 20
#define BSTR (GBN + 8)   // 72

template <bool TA, bool TB, int EPI, bool ACVT, bool BCVT>
__global__ __launch_bounds__(GTHREADS)
void mma_gemm(const float* __restrict__ A, const float* __restrict__ B,
              float* __restrict__ C,
              int M, int N, int K, int lda, int ldb, int ldc,
              const float* __restrict__ rowscale) {
    __shared__ uint32_t As[2][GBM][ASTR];
    __shared__ uint32_t Bs[2][GBK][BSTR];

    int tid = threadIdx.x;
    int lane = tid & 31;
    int warp = tid >> 5;
    int gid = lane >> 2, tig = lane & 3;
    int mw = (warp & 1) * 32;
    int nw = (warp >> 1) * 32;
    int bm = blockIdx.y * GBM;
    int bn = blockIdx.x * GBN;

    float acc[2][4][4];
    #pragma unroll
    for (int i = 0; i < 2; i++)
        #pragma unroll
        for (int j = 0; j < 4; j++)
            #pragma unroll
            for (int l = 0; l < 4; l++) acc[i][j][l] = 0.f;

    uint32_t ra[8];
    uint32_t rb[8];

    int nkt = (K + GBK - 1) / GBK;

    // ---------- raw-bit staging (no math in loaders) ----------
    auto load_regs = [&](int kt) {
        int k0 = kt * GBK;
        if (!TA) {
            int m0 = tid >> 1;
            int kq = (tid & 1) * 8;
            int gm = bm + m0;
            #pragma unroll
            for (int p = 0; p < 2; p++) {
                int gk = k0 + kq + p * 4;
                uint4 v = make_uint4(0u, 0u, 0u, 0u);
                if (gm < M && gk < K)
                    v = *reinterpret_cast<const uint4*>(&A[(size_t)gm * lda + gk]);
                ra[p * 4 + 0] = v.x; ra[p * 4 + 1] = v.y;
                ra[p * 4 + 2] = v.z; ra[p * 4 + 3] = v.w;
            }
        } else {
            int kq = tid >> 4;
            int m4 = (tid & 15) * 4;
            int gm = bm + m4;
            #pragma unroll
            for (int p = 0; p < 2; p++) {
                int gk = k0 + kq + p * 8;
                uint4 v = make_uint4(0u, 0u, 0u, 0u);
                if (gk < K && gm < M)
                    v = *reinterpret_cast<const uint4*>(&A[(size_t)gk * lda + gm]);
                ra[p * 4 + 0] = v.x; ra[p * 4 + 1] = v.y;
                ra[p * 4 + 2] = v.z; ra[p * 4 + 3] = v.w;
            }
        }
        if (!TB) {
            int kb = tid >> 3;
            int nq = (tid & 7) * 8;
            int gk = k0 + kb;
            #pragma unroll
            for (int p = 0; p < 2; p++) {
                int gn = bn + nq + p * 4;
                uint4 v = make_uint4(0u, 0u, 0u, 0u);
                if (gk < K && gn < N)
                    v = *reinterpret_cast<const uint4*>(&B[(size_t)gk * ldb + gn]);
                rb[p * 4 + 0] = v.x; rb[p * 4 + 1] = v.y;
                rb[p * 4 + 2] = v.z; rb[p * 4 + 3] = v.w;
            }
        } else {
            int nq = tid >> 1;
            int kq = (tid & 1) * 8;
            int gn = bn + nq;
            #pragma unroll
            for (int p = 0; p < 2; p++) {
                int gk = k0 + kq + p * 4;
                uint4 v = make_uint4(0u, 0u, 0u, 0u);
                if (gn < N && gk < K)
                    v = *reinterpret_cast<const uint4*>(&B[(size_t)gn * ldb + gk]);
                rb[p * 4 + 0] = v.x; rb[p * 4 + 1] = v.y;
                rb[p * 4 + 2] = v.z; rb[p * 4 + 3] = v.w;
            }
        }
    };

    auto store_smem = [&](int buf) {
        if (!TA) {
            int m0 = tid >> 1;
            int kq = (tid & 1) * 8;
            *reinterpret_cast<uint4*>(&As[buf][m0][kq]) =
                make_uint4(ra[0], ra[1], ra[2], ra[3]);
            *reinterpret_cast<uint4*>(&As[buf][m0][kq + 4]) =
                make_uint4(ra[4], ra[5], ra[6], ra[7]);
        } else {
            int kq = tid >> 4;
            int m4 = (tid & 15) * 4;
            #pragma unroll
            for (int p = 0; p < 2; p++) {
                int k = kq + p * 8;
                As[buf][m4 + 0][k] = ra[p * 4 + 0];
                As[buf][m4 + 1][k] = ra[p * 4 + 1];
                As[buf][m4 + 2][k] = ra[p * 4 + 2];
                As[buf][m4 + 3][k] = ra[p * 4 + 3];
            }
        }
        if (!TB) {
            int kb = tid >> 3;
            int nq = (tid & 7) * 8;
            *reinterpret_cast<uint4*>(&Bs[buf][kb][nq]) =
                make_uint4(rb[0], rb[1], rb[2], rb[3]);
            *reinterpret_cast<uint4*>(&Bs[buf][kb][nq + 4]) =
                make_uint4(rb[4], rb[5], rb[6], rb[7]);
        } else {
            int nq = tid >> 1;
            int kq = (tid & 1) * 8;
            #pragma unroll
            for (int p = 0; p < 2; p++) {
                int k = kq + p * 4;
                Bs[buf][k + 0][nq] = rb[p * 4 + 0];
                Bs[buf][k + 1][nq] = rb[p * 4 + 1];
                Bs[buf][k + 2][nq] = rb[p * 4 + 2];
                Bs[buf][k + 3][nq] = rb[p * 4 + 3];
            }
        }
    };

    load_regs(0);
    store_smem(0);
    __syncthreads();

    for (int kt = 0; kt < nkt; kt++) {
        int cur = kt & 1;
        if (kt + 1 < nkt) load_regs(kt + 1);

        #pragma unroll
        for (int kk = 0; kk < GBK; kk += 8) {
            uint32_t b0[4], b1[4];
            #pragma unroll
            for (int nt = 0; nt < 4; nt++) {
                b0[nt] = Bs[cur][kk + tig][nw + nt * 8 + gid];
                b1[nt] = Bs[cur][kk + tig + 4][nw + nt * 8 + gid];
                if (BCVT) { b0[nt] = cvt_bits(b0[nt]); b1[nt] = cvt_bits(b1[nt]); }
            }
            #pragma unroll
            for (int mt = 0; mt < 2; mt++) {
                int mb = mw + mt * 16;
                uint32_t a0 = As[cur][mb + gid][kk + tig];
                uint32_t a1 = As[cur][mb + gid + 8][kk + tig];
                uint32_t a2 = As[cur][mb + gid][kk + tig + 4];
                uint32_t a3 = As[cur][mb + gid + 8][kk + tig + 4];
                if (ACVT) {
                    a0 = cvt_bits(a0); a1 = cvt_bits(a1);
                    a2 = cvt_bits(a2); a3 = cvt_bits(a3);
                }
                #pragma unroll
                for (int nt = 0; nt < 4; nt++)
                    mma_tf32(acc[mt][nt], a0, a1, a2, a3, b0[nt], b1[nt]);
            }
        }

        if (kt + 1 < nkt) store_smem((kt + 1) & 1);
        __syncthreads();
    }

    // ---------- epilogue ----------
    #pragma unroll
    for (int mt = 0; mt < 2; mt++) {
        int gm0 = bm + mw + mt * 16 + gid;
        int gm1 = gm0 + 8;
        float rs0 = 1.f, rs1 = 1.f;
        if (rowscale) {
            if (gm0 < M) rs0 = rowscale[gm0];
            if (gm1 < M) rs1 = rowscale[gm1];
        }
        #pragma unroll
        for (int nt = 0; nt < 4; nt++) {
            int gn0 = bn + nw + nt * 8 + 2 * tig;
            int gn1 = gn0 + 1;
            #pragma unroll
            for (int q = 0; q < 4; q++) {
                int gm = (q < 2) ? gm0 : gm1;
                int gn = (q & 1) ? gn1 : gn0;
                if (gm >= M || gn >= N) continue;
                float v = acc[mt][nt][q] * ((q < 2) ? rs0 : rs1);
                if (EPI == 1 || EPI == 4) v = fmaxf(v, 0.f);
                else if (EPI == 2) v = 1.f / (1.f + __expf(-v));
                if (EPI >= 3) v = roundtf(v);
                C[(size_t)gm * ldc + gn] = v;
            }
        }
    }
}

static inline dim3 gemm_grid(int M, int N) {
    return dim3((N + GBN - 1) / GBN, (M + GBM - 1) / GBM);
}

// ---------------- host orchestration ----------------
extern "C" void kernel_launch(void* const* d_in, const int* in_sizes, int n_in,
                              void* d_out, int out_size) {
    const float* R    = (const float*)d_in[0];
    const float* Dm   = (const float*)d_in[1];
    const float* Tm   = (const float*)d_in[2];
    const float* H_d  = (const float*)d_in[3];
    const float* H_t  = (const float*)d_in[4];
    const float* W1g[2] = {(const float*)d_in[5], (const float*)d_in[7]};
    const float* W2g[2] = {(const float*)d_in[6], (const float*)d_in[8]};
    const float* Wd[2]  = {(const float*)d_in[9], (const float*)d_in[11]};
    const float* Wt[2]  = {(const float*)d_in[10], (const float*)d_in[12]};
    const float* WdO  = (const float*)d_in[13];
    const float* WtO  = (const float*)d_in[14];
    float* out = (float*)d_out;

    float *S, *catd, *catt, *hdb, *htb, *hdp, *htp, *bsd, *bst;
    float *sd, *st, *nd, *nt, *ntraw, *part, *selval;
    int* selidx;
    cudaGetSymbolAddress((void**)&S,     g_S);
    cudaGetSymbolAddress((void**)&catd,  g_catd);
    cudaGetSymbolAddress((void**)&catt,  g_catt);
    cudaGetSymbolAddress((void**)&hdb,   g_hd);
    cudaGetSymbolAddress((void**)&htb,   g_ht);
    cudaGetSymbolAddress((void**)&hdp,   g_hdp);
    cudaGetSymbolAddress((void**)&htp,   g_htp);
    cudaGetSymbolAddress((void**)&bsd,   g_bsd);
    cudaGetSymbolAddress((void**)&bst,   g_bst);
    cudaGetSymbolAddress((void**)&sd,    g_sd);
    cudaGetSymbolAddress((void**)&st,    g_st);
    cudaGetSymbolAddress((void**)&nd,    g_nd);
    cudaGetSymbolAddress((void**)&nt,    g_nt);
    cudaGetSymbolAddress((void**)&ntraw, g_ntraw);
    cudaGetSymbolAddress((void**)&part,  g_part);
    cudaGetSymbolAddress((void**)&selidx, g_selidx);
    cudaGetSymbolAddress((void**)&selval, g_selval);

    rowsum_rsqrt<<<D_NUM, 256>>>(Dm, D_NUM, D_NUM, sd);
    rowsum_rsqrt<<<T_NUM, 256>>>(Tm, T_NUM, T_NUM, st);

    const float* hd = H_d;
    const float* ht = H_t;
    int F = FEAT;

    for (int lvl = 0; lvl < 2; lvl++) {
        // ---- D/T sym-normalized GEMMs first (launch positions 2..5 on lvl 0) ----
        prescale_round<<<dim3((F + 255) / 256, D_NUM), 256>>>(bsd, hd, sd, D_NUM, F);
        prescale_round<<<dim3((F + 255) / 256, T_NUM), 256>>>(bst, ht, st, T_NUM, F);
        mma_gemm<false, false, 4, true, false><<<gemm_grid(D_NUM, F), GTHREADS>>>(
            Dm, bsd, catd + 2 * F, D_NUM, F, D_NUM, D_NUM, F, 3 * F, sd);
        mma_gemm<false, false, 4, true, false><<<gemm_grid(T_NUM, F), GTHREADS>>>(
            Tm, bst, catt + 2 * F, T_NUM, F, T_NUM, T_NUM, F, 3 * F, st);

        // ---- GL layer ----
        mma_gemm<false, false, 3, true, true><<<gemm_grid(D_NUM, UNITS), GTHREADS>>>(
            hd, W1g[lvl], hdp, D_NUM, UNITS, F, F, UNITS, UNITS, nullptr);
        mma_gemm<false, false, 3, true, true><<<gemm_grid(T_NUM, UNITS), GTHREADS>>>(
            ht, W2g[lvl], htp, T_NUM, UNITS, F, F, UNITS, UNITS, nullptr);
        mma_gemm<false, true, 2, false, false><<<gemm_grid(D_NUM, T_NUM), GTHREADS>>>(
            hdp, htp, S, D_NUM, T_NUM, UNITS, UNITS, UNITS, T_NUM, nullptr);

        zero_vec<<<(T_NUM + 255) / 256, 256>>>(ntraw, T_NUM);
        topk_kernel<<<D_NUM, 256>>>(S, selidx, selval, nd, ntraw);

        // ---- sparse learned-graph CGC ----
        gather_dt<<<D_NUM, 256>>>(selidx, selval, nd, ntraw, ht, F, catd + F, 3 * F);
        zero_strided<<<dim3((F + 255) / 256, T_NUM), 256>>>(catt + F, 3 * F, T_NUM, F);
        scatter_td<<<D_NUM * TOPK, 256>>>(selidx, selval, nd, ntraw, hd, F, catt + F, 3 * F);
        relu_round_strided<<<dim3((F + 255) / 256, T_NUM), 256>>>(catt + F, 3 * F, T_NUM, F);
        copy_round_strided<<<dim3((F + 255) / 256, D_NUM), 256>>>(catd, 3 * F, hd, F, D_NUM, F);
        copy_round_strided<<<dim3((F + 255) / 256, T_NUM), 256>>>(catt, 3 * F, ht, F, T_NUM, F);

        // ---- concat dense + relu (fp32 activations out) ----
        mma_gemm<false, false, 1, false, true><<<gemm_grid(D_NUM, UNITS), GTHREADS>>>(
            catd, Wd[lvl], hdb, D_NUM, UNITS, 3 * F, 3 * F, UNITS, UNITS, nullptr);
        mma_gemm<false, false, 1, false, true><<<gemm_grid(T_NUM, UNITS), GTHREADS>>>(
            catt, Wt[lvl], htb, T_NUM, UNITS, 3 * F, 3 * F, UNITS, UNITS, nullptr);
        hd = hdb; ht = htb; F = UNITS;
    }

    // ---- output CGC on original (dense) R ----
    rowsum_rsqrt<<<D_NUM, 256>>>(R, D_NUM, T_NUM, nd);
    colsum_partial<<<dim3((T_NUM + 255) / 256, NCHUNK), 256>>>(R, D_NUM, T_NUM, part);
    colsum_finish<<<(T_NUM + 255) / 256, 256>>>(part, T_NUM, nt);

    // H_dt = relu(Rn @ ht):  B = nt-scaled ht
    prescale_round<<<dim3((F + 255) / 256, T_NUM), 256>>>(bsd, ht, nt, T_NUM, F);
    mma_gemm<false, false, 4, true, false><<<gemm_grid(D_NUM, F), GTHREADS>>>(
        R, bsd, catd + F, D_NUM, F, T_NUM, T_NUM, F, 3 * F, nd);
    // H_td = relu(Rn^T @ hd):  B = nd-scaled hd
    prescale_round<<<dim3((F + 255) / 256, D_NUM), 256>>>(bst, hd, nd, D_NUM, F);
    mma_gemm<true, false, 4, true, false><<<gemm_grid(T_NUM, F), GTHREADS>>>(
        R, bst, catt + F, T_NUM, F, D_NUM, T_NUM, F, 3 * F, nt);
    // H_dd
    prescale_round<<<dim3((F + 255) / 256, D_NUM), 256>>>(bsd, hd, sd, D_NUM, F);
    mma_gemm<false, false, 4, true, false><<<gemm_grid(D_NUM, F), GTHREADS>>>(
        Dm, bsd, catd + 2 * F, D_NUM, F, D_NUM, D_NUM, F, 3 * F, sd);
    // H_tt
    prescale_round<<<dim3((F + 255) / 256, T_NUM), 256>>>(bst, ht, st, T_NUM, F);
    mma_gemm<false, false, 4, true, false><<<gemm_grid(T_NUM, F), GTHREADS>>>(
        Tm, bst, catt + 2 * F, T_NUM, F, T_NUM, T_NUM, F, 3 * F, st);

    copy_round_strided<<<dim3((F + 255) / 256, D_NUM), 256>>>(catd, 3 * F, hd, F, D_NUM, F);
    copy_round_strided<<<dim3((F + 255) / 256, T_NUM), 256>>>(catt, 3 * F, ht, F, T_NUM, F);

    mma_gemm<false, false, 4, false, true><<<gemm_grid(D_NUM, UNITS), GTHREADS>>>(
        catd, WdO, hdp, D_NUM, UNITS, 3 * F, 3 * F, UNITS, UNITS, nullptr);
    mma_gemm<false, false, 4, false, true><<<gemm_grid(T_NUM, UNITS), GTHREADS>>>(
        catt, WtO, htp, T_NUM, UNITS, 3 * F, 3 * F, UNITS, UNITS, nullptr);

    // R_pred = sigmoid(hd_out @ ht_out^T)
    mma_gemm<false, true, 2, false, false><<<gemm_grid(D_NUM, T_NUM), GTHREADS>>>(
        hdp, htp, out, D_NUM, T_NUM, UNITS, UNITS, UNITS, T_NUM, nullptr);
}

// round 7
// speedup vs baseline: 1.6288x; 1.1856x over previous
#include <cuda_runtime.h>
#include <math.h>
#include <stdint.h>

#define D_NUM 4000
#define T_NUM 2000
#define FEAT  256
#define UNITS 200
#define TOPK  10
#define NCHUNK 16

// ---------------- scratch (device globals; no runtime allocation) ----------------
__device__ float g_S[(size_t)D_NUM * T_NUM];
__device__ float g_RT[(size_t)T_NUM * D_NUM];      // R transposed
__device__ float g_catd[(size_t)D_NUM * 3 * FEAT];
__device__ float g_catt[(size_t)T_NUM * 3 * FEAT];
__device__ float g_hd[(size_t)D_NUM * FEAT];
__device__ float g_ht[(size_t)T_NUM * FEAT];
__device__ float g_hdp[(size_t)D_NUM * UNITS];
__device__ float g_htp[(size_t)T_NUM * UNITS];
__device__ float g_htpT[(size_t)UNITS * T_NUM];    // htp transposed
__device__ float g_bsd[(size_t)D_NUM * FEAT];
__device__ float g_bst[(size_t)D_NUM * FEAT];
__device__ float g_sd[D_NUM];
__device__ float g_st[T_NUM];
__device__ float g_nd[D_NUM];
__device__ float g_nt[T_NUM];
__device__ float g_ntraw[T_NUM];
__device__ float g_part[NCHUNK * T_NUM];
__device__ int   g_selidx[D_NUM * TOPK];
__device__ float g_selval[D_NUM * TOPK];

__device__ __forceinline__ uint32_t f2tf(float x) {
    uint32_t r;
    asm("cvt.rna.tf32.f32 %0, %1;" : "=r"(r) : "f"(x));
    return r;
}
__device__ __forceinline__ float roundtf(float x) {
    return __uint_as_float(f2tf(x));
}

// ---------------- reductions ----------------
__global__ void rowsum_rsqrt(const float* __restrict__ A, int rows, int cols,
                             float* __restrict__ out) {
    int row = blockIdx.x;
    if (row >= rows) return;
    const float* a = A + (size_t)row * cols;
    float s = 0.f;
    for (int j = threadIdx.x; j < cols; j += blockDim.x) s += a[j];
    __shared__ float red[256];
    red[threadIdx.x] = s;
    __syncthreads();
    for (int off = 128; off > 0; off >>= 1) {
        if (threadIdx.x < off) red[threadIdx.x] += red[threadIdx.x + off];
        __syncthreads();
    }
    if (threadIdx.x == 0) {
        float n = red[0];
        if (n == 0.f) n = 1.f;
        out[row] = rsqrtf(n);
    }
}

__global__ void colsum_partial(const float* __restrict__ A, int rows, int cols,
                               float* __restrict__ part) {
    int j = blockIdx.x * blockDim.x + threadIdx.x;
    if (j >= cols) return;
    int chunk = (rows + NCHUNK - 1) / NCHUNK;
    int r0 = blockIdx.y * chunk;
    int r1 = r0 + chunk; if (r1 > rows) r1 = rows;
    float s = 0.f;
    for (int i = r0; i < r1; i++) s += A[(size_t)i * cols + j];
    part[blockIdx.y * cols + j] = s;
}

__global__ void colsum_finish(const float* __restrict__ part, int cols,
                              float* __restrict__ out) {
    int j = blockIdx.x * blockDim.x + threadIdx.x;
    if (j >= cols) return;
    float s = 0.f;
    for (int c = 0; c < NCHUNK; c++) s += part[c * cols + j];
    if (s == 0.f) s = 1.f;
    out[j] = rsqrtf(s);
}

// ---------------- prep / utility kernels ----------------
__global__ void prescale_round(float* __restrict__ dst, const float* __restrict__ src,
                               const float* __restrict__ scale, int rows, int cols) {
    int c = blockIdx.x * blockDim.x + threadIdx.x;
    int r = blockIdx.y;
    if (c < cols && r < rows) {
        size_t o = (size_t)r * cols + c;
        dst[o] = roundtf(scale[r] * src[o]);
    }
}

__global__ void transpose_kernel(float* __restrict__ dst, const float* __restrict__ src,
                                 int rows, int cols) {
    // dst[c][r] = src[r][c];  dst is [cols][rows]
    __shared__ float t[32][33];
    int bx = blockIdx.x * 32, by = blockIdx.y * 32;
    int x = bx + threadIdx.x;
    #pragma unroll
    for (int i = 0; i < 32; i += 8) {
        int y = by + threadIdx.y + i;
        if (x < cols && y < rows) t[threadIdx.y + i][threadIdx.x] = src[(size_t)y * cols + x];
    }
    __syncthreads();
    int x2 = by + threadIdx.x;
    #pragma unroll
    for (int i = 0; i < 32; i += 8) {
        int y2 = bx + threadIdx.y + i;
        if (x2 < rows && y2 < cols) dst[(size_t)y2 * rows + x2] = t[threadIdx.x][threadIdx.y + i];
    }
}

__global__ void zero_vec(float* __restrict__ p, int n) {
    int i = blockIdx.x * blockDim.x + threadIdx.x;
    if (i < n) p[i] = 0.f;
}

__global__ void zero_strided(float* __restrict__ dst, int ld, int rows, int cols) {
    int c = blockIdx.x * blockDim.x + threadIdx.x;
    int r = blockIdx.y;
    if (c < cols && r < rows) dst[(size_t)r * ld + c] = 0.f;
}

__global__ void relu_round_strided(float* __restrict__ dst, int ld, int rows, int cols) {
    int c = blockIdx.x * blockDim.x + threadIdx.x;
    int r = blockIdx.y;
    if (c < cols && r < rows) {
        size_t o = (size_t)r * ld + c;
        dst[o] = roundtf(fmaxf(dst[o], 0.f));
    }
}

__global__ void copy_round_strided(float* __restrict__ dst, int ldd,
                                   const float* __restrict__ src, int lds,
                                   int rows, int cols) {
    int c = blockIdx.x * blockDim.x + threadIdx.x;
    int r = blockIdx.y;
    if (c < cols && r < rows)
        dst[(size_t)r * ldd + c] = roundtf(src[(size_t)r * lds + c]);
}

// ---------------- top-k (min-index tie like stable argsort) ----------------
__global__ void topk_kernel(const float* __restrict__ S,
                            int* __restrict__ selidx, float* __restrict__ selval,
                            float* __restrict__ nd_out, float* __restrict__ ntraw) {
    int row = blockIdx.x;
    int tid = threadIdx.x;
    int lane = tid & 31, wid = tid >> 5;
    const float* srow = S + (size_t)row * T_NUM;

    float v[8];
    #pragma unroll
    for (int i = 0; i < 8; i++) {
        int j = tid + i * 256;
        v[i] = (j < T_NUM) ? srow[j] : -3.f;
    }

    __shared__ float wv[8];
    __shared__ int   wi[8];
    __shared__ int   bidx_s;
    __shared__ int   sel[TOPK];
    __shared__ float selv[TOPK];

    for (int it = 0; it < TOPK; it++) {
        float best = v[0]; int bi = tid;
        #pragma unroll
        for (int i = 1; i < 8; i++) {
            int j = tid + i * 256;
            if (v[i] > best) { best = v[i]; bi = j; }
        }
        #pragma unroll
        for (int off = 16; off > 0; off >>= 1) {
            float ov = __shfl_xor_sync(0xffffffffu, best, off);
            int   oi = __shfl_xor_sync(0xffffffffu, bi, off);
            if (ov > best || (ov == best && oi < bi)) { best = ov; bi = oi; }
        }
        if (lane == 0) { wv[wid] = best; wi[wid] = bi; }
        __syncthreads();
        if (tid == 0) {
            float b = wv[0]; int x = wi[0];
            #pragma unroll
            for (int w = 1; w < 8; w++)
                if (wv[w] > b || (wv[w] == b && wi[w] < x)) { b = wv[w]; x = wi[w]; }
            bidx_s = x; sel[it] = x; selv[it] = b;
        }
        __syncthreads();
        int x = bidx_s;
        if ((x & 255) == tid) v[x >> 8] = -3.f;
    }

    if (tid < TOPK) {
        selidx[row * TOPK + tid] = sel[tid];
        selval[row * TOPK + tid] = selv[tid];
        atomicAdd(&ntraw[sel[tid]], selv[tid]);
    }
    if (tid == 0) {
        float s = 0.f;
        #pragma unroll
        for (int t = 0; t < TOPK; t++) s += selv[t];
        if (s == 0.f) s = 1.f;
        nd_out[row] = rsqrtf(s);
    }
}

// ---------------- sparse CGC kernels ----------------
__global__ void gather_dt(const int* __restrict__ selidx, const float* __restrict__ selval,
                          const float* __restrict__ nd, const float* __restrict__ ntraw,
                          const float* __restrict__ ht, int F,
                          float* __restrict__ outd, int ldo) {
    int d = blockIdx.x;
    __shared__ int   ci[TOPK];
    __shared__ float cw[TOPK];
    if (threadIdx.x < TOPK) {
        int c = selidx[d * TOPK + threadIdx.x];
        float s = ntraw[c];
        if (s == 0.f) s = 1.f;
        ci[threadIdx.x] = c;
        cw[threadIdx.x] = selval[d * TOPK + threadIdx.x] * rsqrtf(s);
    }
    __syncthreads();
    float ndv = nd[d];
    for (int f = threadIdx.x; f < F; f += blockDim.x) {
        float s = 0.f;
        #pragma unroll
        for (int j = 0; j < TOPK; j++) s += cw[j] * ht[(size_t)ci[j] * F + f];
        outd[(size_t)d * ldo + f] = roundtf(fmaxf(s * ndv, 0.f));
    }
}

__global__ void scatter_td(const int* __restrict__ selidx, const float* __restrict__ selval,
                           const float* __restrict__ nd, const float* __restrict__ ntraw,
                           const float* __restrict__ hd, int F,
                           float* __restrict__ outt, int ldo) {
    int e = blockIdx.x;
    int d = e / TOPK;
    int t = selidx[e];
    float s = ntraw[t];
    if (s == 0.f) s = 1.f;
    float w = selval[e] * nd[d] * rsqrtf(s);
    const float* src = hd + (size_t)d * F;
    float* dst = outt + (size_t)t * ldo;
    for (int f = threadIdx.x; f < F; f += blockDim.x)
        atomicAdd(&dst[f], w * src[f]);
}

// ---------------- TF32 tensor-core GEMM with cp.async 3-stage pipeline ----------
// C = EPI( rowscale[m] * sum_k A(m,k)*B(k,n) ), A row-major, B row-major [K,N].
// EPI: 0 none, 1 relu, 2 sigmoid, 3 round, 4 relu+round.
// ACVT/BCVT: cvt.rna.tf32 on fragments (raw fp32 input) vs pre-rounded input.

__device__ __forceinline__ void mma_tf32(float c[4], uint32_t a0, uint32_t a1,
                                         uint32_t a2, uint32_t a3,
                                         uint32_t b0, uint32_t b1) {
    asm volatile(
        "mma.sync.aligned.m16n8k8.row.col.f32.tf32.tf32.f32 "
        "{%0,%1,%2,%3}, {%4,%5,%6,%7}, {%8,%9}, {%0,%1,%2,%3};"
        : "+f"(c[0]), "+f"(c[1]), "+f"(c[2]), "+f"(c[3])
        : "r"(a0), "r"(a1), "r"(a2), "r"(a3), "r"(b0), "r"(b1));
}

__device__ __forceinline__ uint32_t cvt_bits(uint32_t raw) {
    return f2tf(__uint_as_float(raw));
}

__device__ __forceinline__ void cp_async16(uint32_t dst_smem, const void* src, bool pred) {
    int sz = pred ? 16 : 0;
    asm volatile("cp.async.ca.shared.global [%0], [%1], 16, %2;"
                 :: "r"(dst_smem), "l"(src), "r"(sz));
}
#define CP_COMMIT() asm volatile("cp.async.commit_group;")
#define CP_WAIT1()  asm volatile("cp.async.wait_group 1;")

#define GBM 64
#define GBN 64
#define GBK 16
#define NSTAGE 3
#define GTHREADS 128
#define ASTR (GBK + 4)   // 20 words; 80B row stride (16B aligned)
#define BSTR (GBN + 8)   // 72 words; 288B row stride (16B aligned)

template <int EPI, bool ACVT, bool BCVT>
__global__ __launch_bounds__(GTHREADS)
void mma_gemm(const float* __restrict__ A, const float* __restrict__ B,
              float* __restrict__ C,
              int M, int N, int K, int lda, int ldb, int ldc,
              const float* __restrict__ rowscale) {
    __shared__ uint32_t As[NSTAGE][GBM][ASTR];
    __shared__ uint32_t Bs[NSTAGE][GBK][BSTR];

    int tid = threadIdx.x;
    int lane = tid & 31;
    int warp = tid >> 5;
    int gid = lane >> 2, tig = lane & 3;
    int mw = (warp & 1) * 32;
    int nw = (warp >> 1) * 32;
    int bm = blockIdx.y * GBM;
    int bn = blockIdx.x * GBN;

    uint32_t sa = (uint32_t)__cvta_generic_to_shared(&As[0][0][0]);
    uint32_t sb = (uint32_t)__cvta_generic_to_shared(&Bs[0][0][0]);

    float acc[2][4][4];
    #pragma unroll
    for (int i = 0; i < 2; i++)
        #pragma unroll
        for (int j = 0; j < 4; j++)
            #pragma unroll
            for (int l = 0; l < 4; l++) acc[i][j][l] = 0.f;

    int nkt = (K + GBK - 1) / GBK;

    // A: 64r x 16k = 256 16B-chunks, 2/thread.  B: 16k x 64n likewise.
    int a_m0 = tid >> 1;
    int a_kq = (tid & 1) * 8;
    int b_kb = tid >> 3;
    int b_nq = (tid & 7) * 8;

    auto issue_tile = [&](int kt, int st) {
        int k0 = kt * GBK;
        {
            int gm = bm + a_m0;
            const float* src = A + (size_t)gm * lda + k0 + a_kq;
            uint32_t dst = sa + (((st * GBM + a_m0) * ASTR) + a_kq) * 4;
            bool rowok = (gm < M);
            cp_async16(dst,      src,     rowok && (k0 + a_kq     < K));
            cp_async16(dst + 16, src + 4, rowok && (k0 + a_kq + 4 < K));
        }
        {
            int gk = k0 + b_kb;
            const float* src = B + (size_t)gk * ldb + bn + b_nq;
            uint32_t dst = sb + (((st * GBK + b_kb) * BSTR) + b_nq) * 4;
            bool kok = (gk < K);
            cp_async16(dst,      src,     kok && (bn + b_nq     < N));
            cp_async16(dst + 16, src + 4, kok && (bn + b_nq + 4 < N));
        }
    };

    // prologue: stages 0,1
    #pragma unroll
    for (int s = 0; s < NSTAGE - 1; s++) {
        if (s < nkt) issue_tile(s, s);
        CP_COMMIT();
    }

    int cur = 0;
    for (int kt = 0; kt < nkt; kt++) {
        CP_WAIT1();
        __syncthreads();

        #pragma unroll
        for (int kk = 0; kk < GBK; kk += 8) {
            uint32_t b0[4], b1[4];
            #pragma unroll
            for (int nt = 0; nt < 4; nt++) {
                b0[nt] = Bs[cur][kk + tig][nw + nt * 8 + gid];
                b1[nt] = Bs[cur][kk + tig + 4][nw + nt * 8 + gid];
                if (BCVT) { b0[nt] = cvt_bits(b0[nt]); b1[nt] = cvt_bits(b1[nt]); }
            }
            #pragma unroll
            for (int mt = 0; mt < 2; mt++) {
                int mb = mw + mt * 16;
                uint32_t a0 = As[cur][mb + gid][kk + tig];
                uint32_t a1 = As[cur][mb + gid + 8][kk + tig];
                uint32_t a2 = As[cur][mb + gid][kk + tig + 4];
                uint32_t a3 = As[cur][mb + gid + 8][kk + tig + 4];
                if (ACVT) {
                    a0 = cvt_bits(a0); a1 = cvt_bits(a1);
                    a2 = cvt_bits(a2); a3 = cvt_bits(a3);
                }
                #pragma unroll
                for (int nt = 0; nt < 4; nt++)
                    mma_tf32(acc[mt][nt], a0, a1, a2, a3, b0[nt], b1[nt]);
            }
        }

        if (kt + NSTAGE - 1 < nkt) {
            int st = (cur + NSTAGE - 1) % NSTAGE;
            issue_tile(kt + NSTAGE - 1, st);
        }
        CP_COMMIT();
        cur = (cur + 1) % NSTAGE;
    }

    // ---------- epilogue ----------
    #pragma unroll
    for (int mt = 0; mt < 2; mt++) {
        int gm0 = bm + mw + mt * 16 + gid;
        int gm1 = gm0 + 8;
        float rs0 = 1.f, rs1 = 1.f;
        if (rowscale) {
            if (gm0 < M) rs0 = rowscale[gm0];
            if (gm1 < M) rs1 = rowscale[gm1];
        }
        #pragma unroll
        for (int nt = 0; nt < 4; nt++) {
            int gn0 = bn + nw + nt * 8 + 2 * tig;
            int gn1 = gn0 + 1;
            #pragma unroll
            for (int q = 0; q < 4; q++) {
                int gm = (q < 2) ? gm0 : gm1;
                int gn = (q & 1) ? gn1 : gn0;
                if (gm >= M || gn >= N) continue;
                float v = acc[mt][nt][q] * ((q < 2) ? rs0 : rs1);
                if (EPI == 1 || EPI == 4) v = fmaxf(v, 0.f);
                else if (EPI == 2) v = 1.f / (1.f + __expf(-v));
                if (EPI >= 3) v = roundtf(v);
                C[(size_t)gm * ldc + gn] = v;
            }
        }
    }
}

static inline dim3 gemm_grid(int M, int N) {
    return dim3((N + GBN - 1) / GBN, (M + GBM - 1) / GBM);
}
static inline dim3 tr_grid(int rows, int cols) {
    return dim3((cols + 31) / 32, (rows + 31) / 32);
}

// ---------------- host orchestration ----------------
extern "C" void kernel_launch(void* const* d_in, const int* in_sizes, int n_in,
                              void* d_out, int out_size) {
    const float* R    = (const float*)d_in[0];
    const float* Dm   = (const float*)d_in[1];
    const float* Tm   = (const float*)d_in[2];
    const float* H_d  = (const float*)d_in[3];
    const float* H_t  = (const float*)d_in[4];
    const float* W1g[2] = {(const float*)d_in[5], (const float*)d_in[7]};
    const float* W2g[2] = {(const float*)d_in[6], (const float*)d_in[8]};
    const float* Wd[2]  = {(const float*)d_in[9], (const float*)d_in[11]};
    const float* Wt[2]  = {(const float*)d_in[10], (const float*)d_in[12]};
    const float* WdO  = (const float*)d_in[13];
    const float* WtO  = (const float*)d_in[14];
    float* out = (float*)d_out;

    float *S, *RT, *catd, *catt, *hdb, *htb, *hdp, *htp, *htpT, *bsd, *bst;
    float *sd, *st, *nd, *nt, *ntraw, *part, *selval;
    int* selidx;
    cudaGetSymbolAddress((void**)&S,     g_S);
    cudaGetSymbolAddress((void**)&RT,    g_RT);
    cudaGetSymbolAddress((void**)&catd,  g_catd);
    cudaGetSymbolAddress((void**)&catt,  g_catt);
    cudaGetSymbolAddress((void**)&hdb,   g_hd);
    cudaGetSymbolAddress((void**)&htb,   g_ht);
    cudaGetSymbolAddress((void**)&hdp,   g_hdp);
    cudaGetSymbolAddress((void**)&htp,   g_htp);
    cudaGetSymbolAddress((void**)&htpT,  g_htpT);
    cudaGetSymbolAddress((void**)&bsd,   g_bsd);
    cudaGetSymbolAddress((void**)&bst,   g_bst);
    cudaGetSymbolAddress((void**)&sd,    g_sd);
    cudaGetSymbolAddress((void**)&st,    g_st);
    cudaGetSymbolAddress((void**)&nd,    g_nd);
    cudaGetSymbolAddress((void**)&nt,    g_nt);
    cudaGetSymbolAddress((void**)&ntraw, g_ntraw);
    cudaGetSymbolAddress((void**)&part,  g_part);
    cudaGetSymbolAddress((void**)&selidx, g_selidx);
    cudaGetSymbolAddress((void**)&selval, g_selval);

    rowsum_rsqrt<<<D_NUM, 256>>>(Dm, D_NUM, D_NUM, sd);
    rowsum_rsqrt<<<T_NUM, 256>>>(Tm, T_NUM, T_NUM, st);

    const float* hd = H_d;
    const float* ht = H_t;
    int F = FEAT;

    for (int lvl = 0; lvl < 2; lvl++) {
        // ---- D/T sym-normalized GEMMs first (big; representative for ncu) ----
        prescale_round<<<dim3((F + 255) / 256, D_NUM), 256>>>(bsd, hd, sd, D_NUM, F);
        prescale_round<<<dim3((F + 255) / 256, T_NUM), 256>>>(bst, ht, st, T_NUM, F);
        mma_gemm<4, true, false><<<gemm_grid(D_NUM, F), GTHREADS>>>(
            Dm, bsd, catd + 2 * F, D_NUM, F, D_NUM, D_NUM, F, 3 * F, sd);
        mma_gemm<4, true, false><<<gemm_grid(T_NUM, F), GTHREADS>>>(
            Tm, bst, catt + 2 * F, T_NUM, F, T_NUM, T_NUM, F, 3 * F, st);

        // ---- GL layer ----
        mma_gemm<3, true, true><<<gemm_grid(D_NUM, UNITS), GTHREADS>>>(
            hd, W1g[lvl], hdp, D_NUM, UNITS, F, F, UNITS, UNITS, nullptr);
        mma_gemm<3, true, true><<<gemm_grid(T_NUM, UNITS), GTHREADS>>>(
            ht, W2g[lvl], htp, T_NUM, UNITS, F, F, UNITS, UNITS, nullptr);
        transpose_kernel<<<tr_grid(T_NUM, UNITS), dim3(32, 8)>>>(htpT, htp, T_NUM, UNITS);
        mma_gemm<2, false, false><<<gemm_grid(D_NUM, T_NUM), GTHREADS>>>(
            hdp, htpT, S, D_NUM, T_NUM, UNITS, UNITS, T_NUM, T_NUM, nullptr);

        zero_vec<<<(T_NUM + 255) / 256, 256>>>(ntraw, T_NUM);
        topk_kernel<<<D_NUM, 256>>>(S, selidx, selval, nd, ntraw);

        // ---- sparse learned-graph CGC ----
        gather_dt<<<D_NUM, 256>>>(selidx, selval, nd, ntraw, ht, F, catd + F, 3 * F);
        zero_strided<<<dim3((F + 255) / 256, T_NUM), 256>>>(catt + F, 3 * F, T_NUM, F);
        scatter_td<<<D_NUM * TOPK, 256>>>(selidx, selval, nd, ntraw, hd, F, catt + F, 3 * F);
        relu_round_strided<<<dim3((F + 255) / 256, T_NUM), 256>>>(catt + F, 3 * F, T_NUM, F);
        copy_round_strided<<<dim3((F + 255) / 256, D_NUM), 256>>>(catd, 3 * F, hd, F, D_NUM, F);
        copy_round_strided<<<dim3((F + 255) / 256, T_NUM), 256>>>(catt, 3 * F, ht, F, T_NUM, F);

        // ---- concat dense + relu ----
        mma_gemm<1, false, true><<<gemm_grid(D_NUM, UNITS), GTHREADS>>>(
            catd, Wd[lvl], hdb, D_NUM, UNITS, 3 * F, 3 * F, UNITS, UNITS, nullptr);
        mma_gemm<1, false, true><<<gemm_grid(T_NUM, UNITS), GTHREADS>>>(
            catt, Wt[lvl], htb, T_NUM, UNITS, 3 * F, 3 * F, UNITS, UNITS, nullptr);
        hd = hdb; ht = htb; F = UNITS;
    }

    // ---- output CGC on original (dense) R ----
    rowsum_rsqrt<<<D_NUM, 256>>>(R, D_NUM, T_NUM, nd);
    colsum_partial<<<dim3((T_NUM + 255) / 256, NCHUNK), 256>>>(R, D_NUM, T_NUM, part);
    colsum_finish<<<(T_NUM + 255) / 256, 256>>>(part, T_NUM, nt);
    transpose_kernel<<<tr_grid(D_NUM, T_NUM), dim3(32, 8)>>>(RT, R, D_NUM, T_NUM);

    // H_dt = relu(Rn @ ht):  B = nt-scaled ht
    prescale_round<<<dim3((F + 255) / 256, T_NUM), 256>>>(bsd, ht, nt, T_NUM, F);
    mma_gemm<4, true, false><<<gemm_grid(D_NUM, F), GTHREADS>>>(
        R, bsd, catd + F, D_NUM, F, T_NUM, T_NUM, F, 3 * F, nd);
    // H_td = relu(Rn^T @ hd):  A = RT, B = nd-scaled hd
    prescale_round<<<dim3((F + 255) / 256, D_NUM), 256>>>(bst, hd, nd, D_NUM, F);
    mma_gemm<4, true, false><<<gemm_grid(T_NUM, F), GTHREADS>>>(
        RT, bst, catt + F, T_NUM, F, D_NUM, D_NUM, F, 3 * F, nt);
    // H_dd
    prescale_round<<<dim3((F + 255) / 256, D_NUM), 256>>>(bsd, hd, sd, D_NUM, F);
    mma_gemm<4, true, false><<<gemm_grid(D_NUM, F), GTHREADS>>>(
        Dm, bsd, catd + 2 * F, D_NUM, F, D_NUM, D_NUM, F, 3 * F, sd);
    // H_tt
    prescale_round<<<dim3((F + 255) / 256, T_NUM), 256>>>(bst, ht, st, T_NUM, F);
    mma_gemm<4, true, false><<<gemm_grid(T_NUM, F), GTHREADS>>>(
        Tm, bst, catt + 2 * F, T_NUM, F, T_NUM, T_NUM, F, 3 * F, st);

    copy_round_strided<<<dim3((F + 255) / 256, D_NUM), 256>>>(catd, 3 * F, hd, F, D_NUM, F);
    copy_round_strided<<<dim3((F + 255) / 256, T_NUM), 256>>>(catt, 3 * F, ht, F, T_NUM, F);

    mma_gemm<4, false, true><<<gemm_grid(D_NUM, UNITS), GTHREADS>>>(
        catd, WdO, hdp, D_NUM, UNITS, 3 * F, 3 * F, UNITS, UNITS, nullptr);
    mma_gemm<4, false, true><<<gemm_grid(T_NUM, UNITS), GTHREADS>>>(
        catt, WtO, htp, T_NUM, UNITS, 3 * F, 3 * F, UNITS, UNITS, nullptr);

    // R_pred = sigmoid(hd_out @ ht_out^T)
    transpose_kernel<<<tr_grid(T_NUM, UNITS), dim3(32, 8)>>>(htpT, htp, T_NUM, UNITS);
    mma_gemm<2, false, false><<<gemm_grid(D_NUM, T_NUM), GTHREADS>>>(
        hdp, htpT, out, D_NUM, T_NUM, UNITS, UNITS, T_NUM, T_NUM, nullptr);
}

// round 8
// speedup vs baseline: 1.7224x; 1.0574x over previous
#include <cuda_runtime.h>
#include <math.h>
#include <stdint.h>

#define D_NUM 4000
#define T_NUM 2000
#define FEAT  256
#define UNITS 200
#define TOPK  10
#define NCHUNK 16

// ---------------- scratch ----------------
__device__ float g_S[(size_t)D_NUM * T_NUM];
__device__ float g_RT[(size_t)T_NUM * D_NUM];
__device__ float g_catd[(size_t)D_NUM * 3 * FEAT];
__device__ float g_catt[(size_t)T_NUM * 3 * FEAT];
__device__ float g_hd[(size_t)D_NUM * FEAT];
__device__ float g_ht[(size_t)T_NUM * FEAT];
__device__ float g_hdp[(size_t)D_NUM * UNITS];
__device__ float g_htp[(size_t)T_NUM * UNITS];
__device__ float g_htpT[(size_t)UNITS * T_NUM];
__device__ float g_bsd[(size_t)D_NUM * FEAT];
__device__ float g_bst[(size_t)D_NUM * FEAT];
__device__ float g_bsd2[(size_t)D_NUM * FEAT];
__device__ float g_bst2[(size_t)D_NUM * FEAT];
__device__ float g_sd[D_NUM];
__device__ float g_st[T_NUM];
__device__ float g_nd[D_NUM];
__device__ float g_nt[T_NUM];
__device__ float g_ntraw[T_NUM];
__device__ float g_part[NCHUNK * T_NUM];
__device__ int   g_selidx[D_NUM * TOPK];
__device__ float g_selval[D_NUM * TOPK];

__device__ __forceinline__ uint32_t f2tf(float x) {
    uint32_t r;
    asm("cvt.rna.tf32.f32 %0, %1;" : "=r"(r) : "f"(x));
    return r;
}
__device__ __forceinline__ float roundtf(float x) {
    return __uint_as_float(f2tf(x));
}

// ---------------- reductions ----------------
__global__ void rowsum_rsqrt(const float* __restrict__ A, int rows, int cols,
                             float* __restrict__ out) {
    int row = blockIdx.x;
    if (row >= rows) return;
    const float* a = A + (size_t)row * cols;
    float s = 0.f;
    for (int j = threadIdx.x; j < cols; j += blockDim.x) s += a[j];
    __shared__ float red[256];
    red[threadIdx.x] = s;
    __syncthreads();
    for (int off = 128; off > 0; off >>= 1) {
        if (threadIdx.x < off) red[threadIdx.x] += red[threadIdx.x + off];
        __syncthreads();
    }
    if (threadIdx.x == 0) {
        float n = red[0];
        if (n == 0.f) n = 1.f;
        out[row] = rsqrtf(n);
    }
}

__global__ void colsum_partial(const float* __restrict__ A, int rows, int cols,
                               float* __restrict__ part) {
    int j = blockIdx.x * blockDim.x + threadIdx.x;
    if (j >= cols) return;
    int chunk = (rows + NCHUNK - 1) / NCHUNK;
    int r0 = blockIdx.y * chunk;
    int r1 = r0 + chunk; if (r1 > rows) r1 = rows;
    float s = 0.f;
    for (int i = r0; i < r1; i++) s += A[(size_t)i * cols + j];
    part[blockIdx.y * cols + j] = s;
}

__global__ void colsum_finish(const float* __restrict__ part, int cols,
                              float* __restrict__ out) {
    int j = blockIdx.x * blockDim.x + threadIdx.x;
    if (j >= cols) return;
    float s = 0.f;
    for (int c = 0; c < NCHUNK; c++) s += part[c * cols + j];
    if (s == 0.f) s = 1.f;
    out[j] = rsqrtf(s);
}

// ---------------- prep kernels ----------------
// z-fused: dst[r,c] = tf32_round(scale[r]*src[r,c]) for two problems, float4-wide.
__global__ void prescale2(float* dst0, const float* src0, const float* sc0, int rows0,
                          float* dst1, const float* src1, const float* sc1, int rows1,
                          int cols4) {
    int c4 = blockIdx.x * blockDim.x + threadIdx.x;
    int r = blockIdx.y;
    float* dst = blockIdx.z ? dst1 : dst0;
    const float* src = blockIdx.z ? src1 : src0;
    const float* sc = blockIdx.z ? sc1 : sc0;
    int rows = blockIdx.z ? rows1 : rows0;
    if (c4 >= cols4 || r >= rows) return;
    float s = sc[r];
    float4 v = reinterpret_cast<const float4*>(src + (size_t)r * cols4 * 4)[c4];
    v.x = roundtf(v.x * s); v.y = roundtf(v.y * s);
    v.z = roundtf(v.z * s); v.w = roundtf(v.w * s);
    reinterpret_cast<float4*>(dst + (size_t)r * cols4 * 4)[c4] = v;
}

__global__ void transpose_kernel(float* __restrict__ dst, const float* __restrict__ src,
                                 int rows, int cols) {
    __shared__ float t[32][33];
    int bx = blockIdx.x * 32, by = blockIdx.y * 32;
    int x = bx + threadIdx.x;
    #pragma unroll
    for (int i = 0; i < 32; i += 8) {
        int y = by + threadIdx.y + i;
        if (x < cols && y < rows) t[threadIdx.y + i][threadIdx.x] = src[(size_t)y * cols + x];
    }
    __syncthreads();
    int x2 = by + threadIdx.x;
    #pragma unroll
    for (int i = 0; i < 32; i += 8) {
        int y2 = bx + threadIdx.y + i;
        if (x2 < rows && y2 < cols) dst[(size_t)y2 * rows + x2] = t[threadIdx.x][threadIdx.y + i];
    }
}

__global__ void zero_vec(float* __restrict__ p, int n) {
    int i = blockIdx.x * blockDim.x + threadIdx.x;
    if (i < n) p[i] = 0.f;
}

__global__ void zero_strided(float* __restrict__ dst, int ld, int rows, int cols) {
    int c = blockIdx.x * blockDim.x + threadIdx.x;
    int r = blockIdx.y;
    if (c < cols && r < rows) dst[(size_t)r * ld + c] = 0.f;
}

__global__ void relu_round_strided(float* __restrict__ dst, int ld, int rows, int cols) {
    int c = blockIdx.x * blockDim.x + threadIdx.x;
    int r = blockIdx.y;
    if (c < cols && r < rows) {
        size_t o = (size_t)r * ld + c;
        dst[o] = roundtf(fmaxf(dst[o], 0.f));
    }
}

// z-fused pair of strided round-copies (concat identity slices)
__global__ void copy_round2(float* dst0, int ldd0, const float* src0, int lds0, int rows0,
                            float* dst1, int ldd1, const float* src1, int lds1, int rows1,
                            int cols) {
    int c = blockIdx.x * blockDim.x + threadIdx.x;
    int r = blockIdx.y;
    float* dst = blockIdx.z ? dst1 : dst0;
    const float* src = blockIdx.z ? src1 : src0;
    int ldd = blockIdx.z ? ldd1 : ldd0;
    int lds = blockIdx.z ? lds1 : lds0;
    int rows = blockIdx.z ? rows1 : rows0;
    if (c < cols && r < rows)
        dst[(size_t)r * ldd + c] = roundtf(src[(size_t)r * lds + c]);
}

// ---------------- top-k ----------------
__global__ void topk_kernel(const float* __restrict__ S,
                            int* __restrict__ selidx, float* __restrict__ selval,
                            float* __restrict__ nd_out, float* __restrict__ ntraw) {
    int row = blockIdx.x;
    int tid = threadIdx.x;
    int lane = tid & 31, wid = tid >> 5;
    const float* srow = S + (size_t)row * T_NUM;

    float v[8];
    #pragma unroll
    for (int i = 0; i < 8; i++) {
        int j = tid + i * 256;
        v[i] = (j < T_NUM) ? srow[j] : -3.f;
    }

    __shared__ float wv[8];
    __shared__ int   wi[8];
    __shared__ int   bidx_s;
    __shared__ int   sel[TOPK];
    __shared__ float selv[TOPK];

    for (int it = 0; it < TOPK; it++) {
        float best = v[0]; int bi = tid;
        #pragma unroll
        for (int i = 1; i < 8; i++) {
            int j = tid + i * 256;
            if (v[i] > best) { best = v[i]; bi = j; }
        }
        #pragma unroll
        for (int off = 16; off > 0; off >>= 1) {
            float ov = __shfl_xor_sync(0xffffffffu, best, off);
            int   oi = __shfl_xor_sync(0xffffffffu, bi, off);
            if (ov > best || (ov == best && oi < bi)) { best = ov; bi = oi; }
        }
        if (lane == 0) { wv[wid] = best; wi[wid] = bi; }
        __syncthreads();
        if (tid == 0) {
            float b = wv[0]; int x = wi[0];
            #pragma unroll
            for (int w = 1; w < 8; w++)
                if (wv[w] > b || (wv[w] == b && wi[w] < x)) { b = wv[w]; x = wi[w]; }
            bidx_s = x; sel[it] = x; selv[it] = b;
        }
        __syncthreads();
        int x = bidx_s;
        if ((x & 255) == tid) v[x >> 8] = -3.f;
    }

    if (tid < TOPK) {
        selidx[row * TOPK + tid] = sel[tid];
        selval[row * TOPK + tid] = selv[tid];
        atomicAdd(&ntraw[sel[tid]], selv[tid]);
    }
    if (tid == 0) {
        float s = 0.f;
        #pragma unroll
        for (int t = 0; t < TOPK; t++) s += selv[t];
        if (s == 0.f) s = 1.f;
        nd_out[row] = rsqrtf(s);
    }
}

// ---------------- sparse CGC ----------------
__global__ void gather_dt(const int* __restrict__ selidx, const float* __restrict__ selval,
                          const float* __restrict__ nd, const float* __restrict__ ntraw,
                          const float* __restrict__ ht, int F,
                          float* __restrict__ outd, int ldo) {
    int d = blockIdx.x;
    __shared__ int   ci[TOPK];
    __shared__ float cw[TOPK];
    if (threadIdx.x < TOPK) {
        int c = selidx[d * TOPK + threadIdx.x];
        float s = ntraw[c];
        if (s == 0.f) s = 1.f;
        ci[threadIdx.x] = c;
        cw[threadIdx.x] = selval[d * TOPK + threadIdx.x] * rsqrtf(s);
    }
    __syncthreads();
    float ndv = nd[d];
    for (int f = threadIdx.x; f < F; f += blockDim.x) {
        float s = 0.f;
        #pragma unroll
        for (int j = 0; j < TOPK; j++) s += cw[j] * ht[(size_t)ci[j] * F + f];
        outd[(size_t)d * ldo + f] = roundtf(fmaxf(s * ndv, 0.f));
    }
}

__global__ void scatter_td(const int* __restrict__ selidx, const float* __restrict__ selval,
                           const float* __restrict__ nd, const float* __restrict__ ntraw,
                           const float* __restrict__ hd, int F,
                           float* __restrict__ outt, int ldo) {
    int e = blockIdx.x;
    int d = e / TOPK;
    int t = selidx[e];
    float s = ntraw[t];
    if (s == 0.f) s = 1.f;
    float w = selval[e] * nd[d] * rsqrtf(s);
    const float* src = hd + (size_t)d * F;
    float* dst = outt + (size_t)t * ldo;
    for (int f = threadIdx.x; f < F; f += blockDim.x)
        atomicAdd(&dst[f], w * src[f]);
}

// ---------------- TF32 GEMM: cp.async pipeline, 2-problem horizontal fusion ----
struct GemmP {
    const float* A;
    const float* B;
    float* C;
    int M, N, K, lda, ldb, ldc;
    const float* rowscale;
};

__device__ __forceinline__ void mma_tf32(float c[4], uint32_t a0, uint32_t a1,
                                         uint32_t a2, uint32_t a3,
                                         uint32_t b0, uint32_t b1) {
    asm volatile(
        "mma.sync.aligned.m16n8k8.row.col.f32.tf32.tf32.f32 "
        "{%0,%1,%2,%3}, {%4,%5,%6,%7}, {%8,%9}, {%0,%1,%2,%3};"
        : "+f"(c[0]), "+f"(c[1]), "+f"(c[2]), "+f"(c[3])
        : "r"(a0), "r"(a1), "r"(a2), "r"(a3), "r"(b0), "r"(b1));
}

__device__ __forceinline__ uint32_t cvt_bits(uint32_t raw) {
    return f2tf(__uint_as_float(raw));
}

__device__ __forceinline__ void cp_async16(uint32_t dst_smem, const void* src, bool pred) {
    int sz = pred ? 16 : 0;
    asm volatile("cp.async.ca.shared.global [%0], [%1], 16, %2;"
                 :: "r"(dst_smem), "l"(src), "r"(sz));
}
#define CP_COMMIT() asm volatile("cp.async.commit_group;")
#define CP_WAIT1()  asm volatile("cp.async.wait_group 1;")

#define GBM 64
#define GBN 64
#define GBK 16
#define NSTAGE 3
#define GTHREADS 128
#define ASTR (GBK + 4)
#define BSTR (GBN + 8)

template <int EPI, bool ACVT, bool BCVT>
__global__ __launch_bounds__(GTHREADS)
void mma_gemm_f(GemmP p0, GemmP p1) {
    const GemmP p = blockIdx.z ? p1 : p0;
    int bm = blockIdx.y * GBM;
    int bn = blockIdx.x * GBN;
    if (bm >= p.M || bn >= p.N) return;

    __shared__ uint32_t As[NSTAGE][GBM][ASTR];
    __shared__ uint32_t Bs[NSTAGE][GBK][BSTR];

    int tid = threadIdx.x;
    int lane = tid & 31;
    int warp = tid >> 5;
    int gid = lane >> 2, tig = lane & 3;
    int mw = (warp & 1) * 32;
    int nw = (warp >> 1) * 32;

    uint32_t sa = (uint32_t)__cvta_generic_to_shared(&As[0][0][0]);
    uint32_t sb = (uint32_t)__cvta_generic_to_shared(&Bs[0][0][0]);

    float acc[2][4][4];
    #pragma unroll
    for (int i = 0; i < 2; i++)
        #pragma unroll
        for (int j = 0; j < 4; j++)
            #pragma unroll
            for (int l = 0; l < 4; l++) acc[i][j][l] = 0.f;

    int nkt = (p.K + GBK - 1) / GBK;

    int a_m0 = tid >> 1;
    int a_kq = (tid & 1) * 8;
    int b_kb = tid >> 3;
    int b_nq = (tid & 7) * 8;

    auto issue_tile = [&](int kt, int st) {
        int k0 = kt * GBK;
        {
            int gm = bm + a_m0;
            const float* src = p.A + (size_t)gm * p.lda + k0 + a_kq;
            uint32_t dst = sa + (((st * GBM + a_m0) * ASTR) + a_kq) * 4;
            bool rowok = (gm < p.M);
            cp_async16(dst,      src,     rowok && (k0 + a_kq     < p.K));
            cp_async16(dst + 16, src + 4, rowok && (k0 + a_kq + 4 < p.K));
        }
        {
            int gk = k0 + b_kb;
            const float* src = p.B + (size_t)gk * p.ldb + bn + b_nq;
            uint32_t dst = sb + (((st * GBK + b_kb) * BSTR) + b_nq) * 4;
            bool kok = (gk < p.K);
            cp_async16(dst,      src,     kok && (bn + b_nq     < p.N));
            cp_async16(dst + 16, src + 4, kok && (bn + b_nq + 4 < p.N));
        }
    };

    #pragma unroll
    for (int s = 0; s < NSTAGE - 1; s++) {
        if (s < nkt) issue_tile(s, s);
        CP_COMMIT();
    }

    int cur = 0;
    for (int kt = 0; kt < nkt; kt++) {
        CP_WAIT1();
        __syncthreads();

        #pragma unroll
        for (int kk = 0; kk < GBK; kk += 8) {
            uint32_t b0[4], b1[4];
            #pragma unroll
            for (int nt = 0; nt < 4; nt++) {
                b0[nt] = Bs[cur][kk + tig][nw + nt * 8 + gid];
                b1[nt] = Bs[cur][kk + tig + 4][nw + nt * 8 + gid];
                if (BCVT) { b0[nt] = cvt_bits(b0[nt]); b1[nt] = cvt_bits(b1[nt]); }
            }
            #pragma unroll
            for (int mt = 0; mt < 2; mt++) {
                int mb = mw + mt * 16;
                uint32_t a0 = As[cur][mb + gid][kk + tig];
                uint32_t a1 = As[cur][mb + gid + 8][kk + tig];
                uint32_t a2 = As[cur][mb + gid][kk + tig + 4];
                uint32_t a3 = As[cur][mb + gid + 8][kk + tig + 4];
                if (ACVT) {
                    a0 = cvt_bits(a0); a1 = cvt_bits(a1);
                    a2 = cvt_bits(a2); a3 = cvt_bits(a3);
                }
                #pragma unroll
                for (int nt = 0; nt < 4; nt++)
                    mma_tf32(acc[mt][nt], a0, a1, a2, a3, b0[nt], b1[nt]);
            }
        }

        if (kt + NSTAGE - 1 < nkt) {
            int st = (cur + NSTAGE - 1) % NSTAGE;
            issue_tile(kt + NSTAGE - 1, st);
        }
        CP_COMMIT();
        cur = (cur + 1) % NSTAGE;
    }

    #pragma unroll
    for (int mt = 0; mt < 2; mt++) {
        int gm0 = bm + mw + mt * 16 + gid;
        int gm1 = gm0 + 8;
        float rs0 = 1.f, rs1 = 1.f;
        if (p.rowscale) {
            if (gm0 < p.M) rs0 = p.rowscale[gm0];
            if (gm1 < p.M) rs1 = p.rowscale[gm1];
        }
        #pragma unroll
        for (int nt = 0; nt < 4; nt++) {
            int gn0 = bn + nw + nt * 8 + 2 * tig;
            int gn1 = gn0 + 1;
            #pragma unroll
            for (int q = 0; q < 4; q++) {
                int gm = (q < 2) ? gm0 : gm1;
                int gn = (q & 1) ? gn1 : gn0;
                if (gm >= p.M || gn >= p.N) continue;
                float v = acc[mt][nt][q] * ((q < 2) ? rs0 : rs1);
                if (EPI == 1 || EPI == 4) v = fmaxf(v, 0.f);
                else if (EPI == 2) v = 1.f / (1.f + __expf(-v));
                if (EPI >= 3) v = roundtf(v);
                p.C[(size_t)gm * p.ldc + gn] = v;
            }
        }
    }
}

static inline GemmP mk(const float* A, const float* B, float* C,
                       int M, int N, int K, int lda, int ldb, int ldc,
                       const float* rs) {
    GemmP p; p.A = A; p.B = B; p.C = C; p.M = M; p.N = N; p.K = K;
    p.lda = lda; p.ldb = ldb; p.ldc = ldc; p.rowscale = rs; return p;
}
static inline dim3 grid1(const GemmP& p) {
    return dim3((p.N + GBN - 1) / GBN, (p.M + GBM - 1) / GBM, 1);
}
static inline dim3 grid2(const GemmP& a, const GemmP& b) {
    int gx = max((a.N + GBN - 1) / GBN, (b.N + GBN - 1) / GBN);
    int gy = max((a.M + GBM - 1) / GBM, (b.M + GBM - 1) / GBM);
    return dim3(gx, gy, 2);
}
static inline dim3 tr_grid(int rows, int cols) {
    return dim3((cols + 31) / 32, (rows + 31) / 32);
}

// ---------------- host orchestration ----------------
extern "C" void kernel_launch(void* const* d_in, const int* in_sizes, int n_in,
                              void* d_out, int out_size) {
    const float* R    = (const float*)d_in[0];
    const float* Dm   = (const float*)d_in[1];
    const float* Tm   = (const float*)d_in[2];
    const float* H_d  = (const float*)d_in[3];
    const float* H_t  = (const float*)d_in[4];
    const float* W1g[2] = {(const float*)d_in[5], (const float*)d_in[7]};
    const float* W2g[2] = {(const float*)d_in[6], (const float*)d_in[8]};
    const float* Wd[2]  = {(const float*)d_in[9], (const float*)d_in[11]};
    const float* Wt[2]  = {(const float*)d_in[10], (const float*)d_in[12]};
    const float* WdO  = (const float*)d_in[13];
    const float* WtO  = (const float*)d_in[14];
    float* out = (float*)d_out;

    float *S, *RT, *catd, *catt, *hdb, *htb, *hdp, *htp, *htpT;
    float *bsd, *bst, *bsd2, *bst2;
    float *sd, *st, *nd, *nt, *ntraw, *part, *selval;
    int* selidx;
    cudaGetSymbolAddress((void**)&S,     g_S);
    cudaGetSymbolAddress((void**)&RT,    g_RT);
    cudaGetSymbolAddress((void**)&catd,  g_catd);
    cudaGetSymbolAddress((void**)&catt,  g_catt);
    cudaGetSymbolAddress((void**)&hdb,   g_hd);
    cudaGetSymbolAddress((void**)&htb,   g_ht);
    cudaGetSymbolAddress((void**)&hdp,   g_hdp);
    cudaGetSymbolAddress((void**)&htp,   g_htp);
    cudaGetSymbolAddress((void**)&htpT,  g_htpT);
    cudaGetSymbolAddress((void**)&bsd,   g_bsd);
    cudaGetSymbolAddress((void**)&bst,   g_bst);
    cudaGetSymbolAddress((void**)&bsd2,  g_bsd2);
    cudaGetSymbolAddress((void**)&bst2,  g_bst2);
    cudaGetSymbolAddress((void**)&sd,    g_sd);
    cudaGetSymbolAddress((void**)&st,    g_st);
    cudaGetSymbolAddress((void**)&nd,    g_nd);
    cudaGetSymbolAddress((void**)&nt,    g_nt);
    cudaGetSymbolAddress((void**)&ntraw, g_ntraw);
    cudaGetSymbolAddress((void**)&part,  g_part);
    cudaGetSymbolAddress((void**)&selidx, g_selidx);
    cudaGetSymbolAddress((void**)&selval, g_selval);

    rowsum_rsqrt<<<D_NUM, 256>>>(Dm, D_NUM, D_NUM, sd);
    rowsum_rsqrt<<<T_NUM, 256>>>(Tm, T_NUM, T_NUM, st);

    const float* hd = H_d;
    const float* ht = H_t;
    int F = FEAT;

    for (int lvl = 0; lvl < 2; lvl++) {
        // prescale pair (hd*sd, ht*st)
        prescale2<<<dim3((F / 4 + 255) / 256, D_NUM, 2), 256>>>(
            bsd, hd, sd, D_NUM, bst, ht, st, T_NUM, F / 4);
        // fused Dn + Tn GEMMs
        {
            GemmP pD = mk(Dm, bsd, catd + 2 * F, D_NUM, F, D_NUM, D_NUM, F, 3 * F, sd);
            GemmP pT = mk(Tm, bst, catt + 2 * F, T_NUM, F, T_NUM, T_NUM, F, 3 * F, st);
            mma_gemm_f<4, true, false><<<grid2(pD, pT), GTHREADS>>>(pD, pT);
        }
        // fused projections
        {
            GemmP pd = mk(hd, W1g[lvl], hdp, D_NUM, UNITS, F, F, UNITS, UNITS, nullptr);
            GemmP pt = mk(ht, W2g[lvl], htp, T_NUM, UNITS, F, F, UNITS, UNITS, nullptr);
            mma_gemm_f<3, true, true><<<grid2(pd, pt), GTHREADS>>>(pd, pt);
        }
        transpose_kernel<<<tr_grid(T_NUM, UNITS), dim3(32, 8)>>>(htpT, htp, T_NUM, UNITS);
        {
            GemmP ps = mk(hdp, htpT, S, D_NUM, T_NUM, UNITS, UNITS, T_NUM, T_NUM, nullptr);
            mma_gemm_f<2, false, false><<<grid1(ps), GTHREADS>>>(ps, ps);
        }

        zero_vec<<<(T_NUM + 255) / 256, 256>>>(ntraw, T_NUM);
        topk_kernel<<<D_NUM, 256>>>(S, selidx, selval, nd, ntraw);

        gather_dt<<<D_NUM, 256>>>(selidx, selval, nd, ntraw, ht, F, catd + F, 3 * F);
        zero_strided<<<dim3((F + 255) / 256, T_NUM), 256>>>(catt + F, 3 * F, T_NUM, F);
        scatter_td<<<D_NUM * TOPK, 256>>>(selidx, selval, nd, ntraw, hd, F, catt + F, 3 * F);
        relu_round_strided<<<dim3((F + 255) / 256, T_NUM), 256>>>(catt + F, 3 * F, T_NUM, F);
        copy_round2<<<dim3((F + 255) / 256, D_NUM, 2), 256>>>(
            catd, 3 * F, hd, F, D_NUM, catt, 3 * F, ht, F, T_NUM, F);

        // fused dense (concat) GEMMs
        {
            GemmP pd = mk(catd, Wd[lvl], hdb, D_NUM, UNITS, 3 * F, 3 * F, UNITS, UNITS, nullptr);
            GemmP pt = mk(catt, Wt[lvl], htb, T_NUM, UNITS, 3 * F, 3 * F, UNITS, UNITS, nullptr);
            mma_gemm_f<1, false, true><<<grid2(pd, pt), GTHREADS>>>(pd, pt);
        }
        hd = hdb; ht = htb; F = UNITS;
    }

    // ---- output CGC on original (dense) R ----
    rowsum_rsqrt<<<D_NUM, 256>>>(R, D_NUM, T_NUM, nd);
    colsum_partial<<<dim3((T_NUM + 255) / 256, NCHUNK), 256>>>(R, D_NUM, T_NUM, part);
    colsum_finish<<<(T_NUM + 255) / 256, 256>>>(part, T_NUM, nt);
    transpose_kernel<<<tr_grid(D_NUM, T_NUM), dim3(32, 8)>>>(RT, R, D_NUM, T_NUM);

    // prescale pairs: (ht*nt, hd*nd) and (hd*sd, ht*st)
    prescale2<<<dim3((F / 4 + 255) / 256, D_NUM, 2), 256>>>(
        bsd, ht, nt, T_NUM, bst, hd, nd, D_NUM, F / 4);
    prescale2<<<dim3((F / 4 + 255) / 256, D_NUM, 2), 256>>>(
        bsd2, hd, sd, D_NUM, bst2, ht, st, T_NUM, F / 4);

    // fused R-pair: H_dt = relu(Rn @ ht), H_td = relu(Rn^T @ hd)
    {
        GemmP pa = mk(R,  bsd, catd + F, D_NUM, F, T_NUM, T_NUM, F, 3 * F, nd);
        GemmP pb = mk(RT, bst, catt + F, T_NUM, F, D_NUM, D_NUM, F, 3 * F, nt);
        mma_gemm_f<4, true, false><<<grid2(pa, pb), GTHREADS>>>(pa, pb);
    }
    // fused Dn/Tn pair
    {
        GemmP pD = mk(Dm, bsd2, catd + 2 * F, D_NUM, F, D_NUM, D_NUM, F, 3 * F, sd);
        GemmP pT = mk(Tm, bst2, catt + 2 * F, T_NUM, F, T_NUM, T_NUM, F, 3 * F, st);
        mma_gemm_f<4, true, false><<<grid2(pD, pT), GTHREADS>>>(pD, pT);
    }

    copy_round2<<<dim3((F + 255) / 256, D_NUM, 2), 256>>>(
        catd, 3 * F, hd, F, D_NUM, catt, 3 * F, ht, F, T_NUM, F);

    // fused output dense
    {
        GemmP pd = mk(catd, WdO, hdp, D_NUM, UNITS, 3 * F, 3 * F, UNITS, UNITS, nullptr);
        GemmP pt = mk(catt, WtO, htp, T_NUM, UNITS, 3 * F, 3 * F, UNITS, UNITS, nullptr);
        mma_gemm_f<4, false, true><<<grid2(pd, pt), GTHREADS>>>(pd, pt);
    }

    // R_pred = sigmoid(hd_out @ ht_out^T)
    transpose_kernel<<<tr_grid(T_NUM, UNITS), dim3(32, 8)>>>(htpT, htp, T_NUM, UNITS);
    {
        GemmP ps = mk(hdp, htpT, out, D_NUM, T_NUM, UNITS, UNITS, T_NUM, T_NUM, nullptr);
        mma_gemm_f<2, false, false><<<grid1(ps), GTHREADS>>>(ps, ps);
    }
}

// round 9
// speedup vs baseline: 2.2105x; 1.2834x over previous
#include <cuda_runtime.h>
#include <math.h>
#include <stdint.h>

#define D_NUM 4000
#define T_NUM 2000
#define FEAT  256
#define UNITS 200
#define TOPK  10
#define NCHUNK 16

// ---------------- scratch ----------------
__device__ float g_S[(size_t)D_NUM * T_NUM];
__device__ float g_RT[(size_t)T_NUM * D_NUM];
__device__ float g_catd[(size_t)D_NUM * 3 * FEAT];
__device__ float g_catt[(size_t)T_NUM * 3 * FEAT];
__device__ float g_hd[(size_t)D_NUM * FEAT];
__device__ float g_ht[(size_t)T_NUM * FEAT];
__device__ float g_hdp[(size_t)D_NUM * UNITS];
__device__ float g_htp[(size_t)T_NUM * UNITS];
__device__ float g_htpT[(size_t)UNITS * T_NUM];
__device__ float g_bsd[(size_t)D_NUM * FEAT];
__device__ float g_bst[(size_t)D_NUM * FEAT];
__device__ float g_bsd2[(size_t)D_NUM * FEAT];
__device__ float g_bst2[(size_t)D_NUM * FEAT];
__device__ float g_pa[(size_t)2 * D_NUM * FEAT];   // split-K partials, problem 0
__device__ float g_pb[(size_t)2 * D_NUM * FEAT];   // split-K partials, problem 1
__device__ float g_sd[D_NUM];
__device__ float g_st[T_NUM];
__device__ float g_nd[D_NUM];
__device__ float g_nt[T_NUM];
__device__ float g_ntraw[T_NUM];
__device__ float g_part[NCHUNK * T_NUM];
__device__ int   g_selidx[D_NUM * TOPK];
__device__ float g_selval[D_NUM * TOPK];

__device__ __forceinline__ uint32_t f2tf(float x) {
    uint32_t r;
    asm("cvt.rna.tf32.f32 %0, %1;" : "=r"(r) : "f"(x));
    return r;
}
__device__ __forceinline__ float roundtf(float x) {
    return __uint_as_float(f2tf(x));
}

// ---------------- reductions ----------------
__global__ void rowsum_rsqrt(const float* __restrict__ A, int rows, int cols,
                             float* __restrict__ out) {
    int row = blockIdx.x;
    if (row >= rows) return;
    const float* a = A + (size_t)row * cols;
    float s = 0.f;
    for (int j = threadIdx.x; j < cols; j += blockDim.x) s += a[j];
    __shared__ float red[256];
    red[threadIdx.x] = s;
    __syncthreads();
    for (int off = 128; off > 0; off >>= 1) {
        if (threadIdx.x < off) red[threadIdx.x] += red[threadIdx.x + off];
        __syncthreads();
    }
    if (threadIdx.x == 0) {
        float n = red[0];
        if (n == 0.f) n = 1.f;
        out[row] = rsqrtf(n);
    }
}

__global__ void colsum_partial(const float* __restrict__ A, int rows, int cols,
                               float* __restrict__ part) {
    int j = blockIdx.x * blockDim.x + threadIdx.x;
    if (j >= cols) return;
    int chunk = (rows + NCHUNK - 1) / NCHUNK;
    int r0 = blockIdx.y * chunk;
    int r1 = r0 + chunk; if (r1 > rows) r1 = rows;
    float s = 0.f;
    for (int i = r0; i < r1; i++) s += A[(size_t)i * cols + j];
    part[blockIdx.y * cols + j] = s;
}

__global__ void colsum_finish(const float* __restrict__ part, int cols,
                              float* __restrict__ out) {
    int j = blockIdx.x * blockDim.x + threadIdx.x;
    if (j >= cols) return;
    float s = 0.f;
    for (int c = 0; c < NCHUNK; c++) s += part[c * cols + j];
    if (s == 0.f) s = 1.f;
    out[j] = rsqrtf(s);
}

// ---------------- prep kernels ----------------
__global__ void prescale2(float* dst0, const float* src0, const float* sc0, int rows0,
                          float* dst1, const float* src1, const float* sc1, int rows1,
                          int cols4) {
    int c4 = blockIdx.x * blockDim.x + threadIdx.x;
    int r = blockIdx.y;
    float* dst = blockIdx.z ? dst1 : dst0;
    const float* src = blockIdx.z ? src1 : src0;
    const float* sc = blockIdx.z ? sc1 : sc0;
    int rows = blockIdx.z ? rows1 : rows0;
    if (c4 >= cols4 || r >= rows) return;
    float s = sc[r];
    float4 v = reinterpret_cast<const float4*>(src + (size_t)r * cols4 * 4)[c4];
    v.x = roundtf(v.x * s); v.y = roundtf(v.y * s);
    v.z = roundtf(v.z * s); v.w = roundtf(v.w * s);
    reinterpret_cast<float4*>(dst + (size_t)r * cols4 * 4)[c4] = v;
}

__global__ void transpose_kernel(float* __restrict__ dst, const float* __restrict__ src,
                                 int rows, int cols) {
    __shared__ float t[32][33];
    int bx = blockIdx.x * 32, by = blockIdx.y * 32;
    int x = bx + threadIdx.x;
    #pragma unroll
    for (int i = 0; i < 32; i += 8) {
        int y = by + threadIdx.y + i;
        if (x < cols && y < rows) t[threadIdx.y + i][threadIdx.x] = src[(size_t)y * cols + x];
    }
    __syncthreads();
    int x2 = by + threadIdx.x;
    #pragma unroll
    for (int i = 0; i < 32; i += 8) {
        int y2 = bx + threadIdx.y + i;
        if (x2 < rows && y2 < cols) dst[(size_t)y2 * rows + x2] = t[threadIdx.x][threadIdx.y + i];
    }
}

__global__ void zero_vec(float* __restrict__ p, int n) {
    int i = blockIdx.x * blockDim.x + threadIdx.x;
    if (i < n) p[i] = 0.f;
}

__global__ void zero_strided(float* __restrict__ dst, int ld, int rows, int cols) {
    int c = blockIdx.x * blockDim.x + threadIdx.x;
    int r = blockIdx.y;
    if (c < cols && r < rows) dst[(size_t)r * ld + c] = 0.f;
}

__global__ void relu_round_strided(float* __restrict__ dst, int ld, int rows, int cols) {
    int c = blockIdx.x * blockDim.x + threadIdx.x;
    int r = blockIdx.y;
    if (c < cols && r < rows) {
        size_t o = (size_t)r * ld + c;
        dst[o] = roundtf(fmaxf(dst[o], 0.f));
    }
}

__global__ void copy_round2(float* dst0, int ldd0, const float* src0, int lds0, int rows0,
                            float* dst1, int ldd1, const float* src1, int lds1, int rows1,
                            int cols) {
    int c = blockIdx.x * blockDim.x + threadIdx.x;
    int r = blockIdx.y;
    float* dst = blockIdx.z ? dst1 : dst0;
    const float* src = blockIdx.z ? src1 : src0;
    int ldd = blockIdx.z ? ldd1 : ldd0;
    int lds = blockIdx.z ? lds1 : lds0;
    int rows = blockIdx.z ? rows1 : rows0;
    if (c < cols && r < rows)
        dst[(size_t)r * ldd + c] = roundtf(src[(size_t)r * lds + c]);
}

// split-K reduce + epilogue, z-fused pair.
// out = EPI( rs[r] * (part[0]+part[1]) );  EPI: 1 relu, 4 relu+round.
template <int EPI>
__global__ void reduce2(float* out0, int ld0, const float* part0, const float* rs0, int M0, int N0,
                        float* out1, int ld1, const float* part1, const float* rs1, int M1, int N1) {
    int c = blockIdx.x * blockDim.x + threadIdx.x;
    int r = blockIdx.y;
    float* out = blockIdx.z ? out1 : out0;
    const float* part = blockIdx.z ? part1 : part0;
    const float* rs = blockIdx.z ? rs1 : rs0;
    int M = blockIdx.z ? M1 : M0;
    int N = blockIdx.z ? N1 : N0;
    int ld = blockIdx.z ? ld1 : ld0;
    if (r >= M || c >= N) return;
    size_t o = (size_t)r * N + c;
    float v = part[o] + part[(size_t)M * N + o];
    if (rs) v *= rs[r];
    if (EPI == 1 || EPI == 4) v = fmaxf(v, 0.f);
    if (EPI >= 3) v = roundtf(v);
    out[(size_t)r * ld + c] = v;
}

// ---------------- top-k ----------------
__global__ void topk_kernel(const float* __restrict__ S,
                            int* __restrict__ selidx, float* __restrict__ selval,
                            float* __restrict__ nd_out, float* __restrict__ ntraw) {
    int row = blockIdx.x;
    int tid = threadIdx.x;
    int lane = tid & 31, wid = tid >> 5;
    const float* srow = S + (size_t)row * T_NUM;

    float v[8];
    #pragma unroll
    for (int i = 0; i < 8; i++) {
        int j = tid + i * 256;
        v[i] = (j < T_NUM) ? srow[j] : -3.f;
    }

    __shared__ float wv[8];
    __shared__ int   wi[8];
    __shared__ int   bidx_s;
    __shared__ int   sel[TOPK];
    __shared__ float selv[TOPK];

    for (int it = 0; it < TOPK; it++) {
        float best = v[0]; int bi = tid;
        #pragma unroll
        for (int i = 1; i < 8; i++) {
            int j = tid + i * 256;
            if (v[i] > best) { best = v[i]; bi = j; }
        }
        #pragma unroll
        for (int off = 16; off > 0; off >>= 1) {
            float ov = __shfl_xor_sync(0xffffffffu, best, off);
            int   oi = __shfl_xor_sync(0xffffffffu, bi, off);
            if (ov > best || (ov == best && oi < bi)) { best = ov; bi = oi; }
        }
        if (lane == 0) { wv[wid] = best; wi[wid] = bi; }
        __syncthreads();
        if (tid == 0) {
            float b = wv[0]; int x = wi[0];
            #pragma unroll
            for (int w = 1; w < 8; w++)
                if (wv[w] > b || (wv[w] == b && wi[w] < x)) { b = wv[w]; x = wi[w]; }
            bidx_s = x; sel[it] = x; selv[it] = b;
        }
        __syncthreads();
        int x = bidx_s;
        if ((x & 255) == tid) v[x >> 8] = -3.f;
    }

    if (tid < TOPK) {
        selidx[row * TOPK + tid] = sel[tid];
        selval[row * TOPK + tid] = selv[tid];
        atomicAdd(&ntraw[sel[tid]], selv[tid]);
    }
    if (tid == 0) {
        float s = 0.f;
        #pragma unroll
        for (int t = 0; t < TOPK; t++) s += selv[t];
        if (s == 0.f) s = 1.f;
        nd_out[row] = rsqrtf(s);
    }
}

// ---------------- sparse CGC ----------------
__global__ void gather_dt(const int* __restrict__ selidx, const float* __restrict__ selval,
                          const float* __restrict__ nd, const float* __restrict__ ntraw,
                          const float* __restrict__ ht, int F,
                          float* __restrict__ outd, int ldo) {
    int d = blockIdx.x;
    __shared__ int   ci[TOPK];
    __shared__ float cw[TOPK];
    if (threadIdx.x < TOPK) {
        int c = selidx[d * TOPK + threadIdx.x];
        float s = ntraw[c];
        if (s == 0.f) s = 1.f;
        ci[threadIdx.x] = c;
        cw[threadIdx.x] = selval[d * TOPK + threadIdx.x] * rsqrtf(s);
    }
    __syncthreads();
    float ndv = nd[d];
    for (int f = threadIdx.x; f < F; f += blockDim.x) {
        float s = 0.f;
        #pragma unroll
        for (int j = 0; j < TOPK; j++) s += cw[j] * ht[(size_t)ci[j] * F + f];
        outd[(size_t)d * ldo + f] = roundtf(fmaxf(s * ndv, 0.f));
    }
}

__global__ void scatter_td(const int* __restrict__ selidx, const float* __restrict__ selval,
                           const float* __restrict__ nd, const float* __restrict__ ntraw,
                           const float* __restrict__ hd, int F,
                           float* __restrict__ outt, int ldo) {
    int e = blockIdx.x;
    int d = e / TOPK;
    int t = selidx[e];
    float s = ntraw[t];
    if (s == 0.f) s = 1.f;
    float w = selval[e] * nd[d] * rsqrtf(s);
    const float* src = hd + (size_t)d * F;
    float* dst = outt + (size_t)t * ldo;
    for (int f = threadIdx.x; f < F; f += blockDim.x)
        atomicAdd(&dst[f], w * src[f]);
}

// ---------------- TF32 GEMM: cp.async pipeline, pair-fused, optional split-K ----
struct GemmP {
    const float* A;
    const float* B;
    float* C;            // output, or split-K partial base (ld = N, 2 slabs)
    int M, N, K, lda, ldb, ldc;
    const float* rowscale;
};

__device__ __forceinline__ void mma_tf32(float c[4], uint32_t a0, uint32_t a1,
                                         uint32_t a2, uint32_t a3,
                                         uint32_t b0, uint32_t b1) {
    asm volatile(
        "mma.sync.aligned.m16n8k8.row.col.f32.tf32.tf32.f32 "
        "{%0,%1,%2,%3}, {%4,%5,%6,%7}, {%8,%9}, {%0,%1,%2,%3};"
        : "+f"(c[0]), "+f"(c[1]), "+f"(c[2]), "+f"(c[3])
        : "r"(a0), "r"(a1), "r"(a2), "r"(a3), "r"(b0), "r"(b1));
}

__device__ __forceinline__ uint32_t cvt_bits(uint32_t raw) {
    return f2tf(__uint_as_float(raw));
}

__device__ __forceinline__ void cp_async16(uint32_t dst_smem, const void* src, bool pred) {
    int sz = pred ? 16 : 0;
    asm volatile("cp.async.cg.shared.global [%0], [%1], 16, %2;"
                 :: "r"(dst_smem), "l"(src), "r"(sz));
}
#define CP_COMMIT() asm volatile("cp.async.commit_group;")
#define CP_WAIT1()  asm volatile("cp.async.wait_group 1;")

#define GBM 64
#define GBN 64
#define GBK 16
#define NSTAGE 3
#define GTHREADS 128
#define ASTR (GBK + 4)
#define BSTR (GBN + 8)

template <int EPI, bool ACVT, bool BCVT, bool SPLIT>
__global__ __launch_bounds__(GTHREADS)
void mma_gemm_f(GemmP p0, GemmP p1) {
    int prob = SPLIT ? (blockIdx.z >> 1) : blockIdx.z;
    int split = SPLIT ? (blockIdx.z & 1) : 0;
    const GemmP p = prob ? p1 : p0;
    int bm = blockIdx.y * GBM;
    int bn = blockIdx.x * GBN;
    if (bm >= p.M || bn >= p.N) return;

    __shared__ uint32_t As[NSTAGE][GBM][ASTR];
    __shared__ uint32_t Bs[NSTAGE][GBK][BSTR];

    int tid = threadIdx.x;
    int lane = tid & 31;
    int warp = tid >> 5;
    int gid = lane >> 2, tig = lane & 3;
    int mw = (warp & 1) * 32;
    int nw = (warp >> 1) * 32;

    uint32_t sa = (uint32_t)__cvta_generic_to_shared(&As[0][0][0]);
    uint32_t sb = (uint32_t)__cvta_generic_to_shared(&Bs[0][0][0]);

    float acc[2][4][4];
    #pragma unroll
    for (int i = 0; i < 2; i++)
        #pragma unroll
        for (int j = 0; j < 4; j++)
            #pragma unroll
            for (int l = 0; l < 4; l++) acc[i][j][l] = 0.f;

    int nkt_total = (p.K + GBK - 1) / GBK;
    int kt_begin = 0, kt_end = nkt_total;
    if (SPLIT) {
        int half = (nkt_total + 1) >> 1;
        kt_begin = split * half;
        kt_end = min(nkt_total, kt_begin + half);
    }
    int niter = kt_end - kt_begin;

    int a_m0 = tid >> 1;
    int a_kq = (tid & 1) * 8;
    int b_kb = tid >> 3;
    int b_nq = (tid & 7) * 8;

    auto issue_tile = [&](int kt, int st) {
        int k0 = kt * GBK;
        {
            int gm = bm + a_m0;
            const float* src = p.A + (size_t)gm * p.lda + k0 + a_kq;
            uint32_t dst = sa + (((st * GBM + a_m0) * ASTR) + a_kq) * 4;
            bool rowok = (gm < p.M);
            cp_async16(dst,      src,     rowok && (k0 + a_kq     < p.K));
            cp_async16(dst + 16, src + 4, rowok && (k0 + a_kq + 4 < p.K));
        }
        {
            int gk = k0 + b_kb;
            const float* src = p.B + (size_t)gk * p.ldb + bn + b_nq;
            uint32_t dst = sb + (((st * GBK + b_kb) * BSTR) + b_nq) * 4;
            bool kok = (gk < p.K);
            cp_async16(dst,      src,     kok && (bn + b_nq     < p.N));
            cp_async16(dst + 16, src + 4, kok && (bn + b_nq + 4 < p.N));
        }
    };

    #pragma unroll
    for (int s = 0; s < NSTAGE - 1; s++) {
        if (s < niter) issue_tile(kt_begin + s, s);
        CP_COMMIT();
    }

    int cur = 0;
    for (int it = 0; it < niter; it++) {
        CP_WAIT1();
        __syncthreads();

        #pragma unroll
        for (int kk = 0; kk < GBK; kk += 8) {
            uint32_t b0[4], b1[4];
            #pragma unroll
            for (int nt = 0; nt < 4; nt++) {
                b0[nt] = Bs[cur][kk + tig][nw + nt * 8 + gid];
                b1[nt] = Bs[cur][kk + tig + 4][nw + nt * 8 + gid];
                if (BCVT) { b0[nt] = cvt_bits(b0[nt]); b1[nt] = cvt_bits(b1[nt]); }
            }
            #pragma unroll
            for (int mt = 0; mt < 2; mt++) {
                int mb = mw + mt * 16;
                uint32_t a0 = As[cur][mb + gid][kk + tig];
                uint32_t a1 = As[cur][mb + gid + 8][kk + tig];
                uint32_t a2 = As[cur][mb + gid][kk + tig + 4];
                uint32_t a3 = As[cur][mb + gid + 8][kk + tig + 4];
                if (ACVT) {
                    a0 = cvt_bits(a0); a1 = cvt_bits(a1);
                    a2 = cvt_bits(a2); a3 = cvt_bits(a3);
                }
                #pragma unroll
                for (int nt = 0; nt < 4; nt++)
                    mma_tf32(acc[mt][nt], a0, a1, a2, a3, b0[nt], b1[nt]);
            }
        }

        if (it + NSTAGE - 1 < niter) {
            int st = (cur + NSTAGE - 1) % NSTAGE;
            issue_tile(kt_begin + it + NSTAGE - 1, st);
        }
        CP_COMMIT();
        cur = (cur + 1) % NSTAGE;
    }

    // ---------- epilogue ----------
    if (SPLIT) {
        float* dst = p.C + (size_t)split * p.M * p.N;
        #pragma unroll
        for (int mt = 0; mt < 2; mt++) {
            int gm0 = bm + mw + mt * 16 + gid;
            int gm1 = gm0 + 8;
            #pragma unroll
            for (int nt = 0; nt < 4; nt++) {
                int gn0 = bn + nw + nt * 8 + 2 * tig;
                int gn1 = gn0 + 1;
                #pragma unroll
                for (int q = 0; q < 4; q++) {
                    int gm = (q < 2) ? gm0 : gm1;
                    int gn = (q & 1) ? gn1 : gn0;
                    if (gm >= p.M || gn >= p.N) continue;
                    dst[(size_t)gm * p.N + gn] = acc[mt][nt][q];
                }
            }
        }
        return;
    }

    #pragma unroll
    for (int mt = 0; mt < 2; mt++) {
        int gm0 = bm + mw + mt * 16 + gid;
        int gm1 = gm0 + 8;
        float rs0 = 1.f, rs1 = 1.f;
        if (p.rowscale) {
            if (gm0 < p.M) rs0 = p.rowscale[gm0];
            if (gm1 < p.M) rs1 = p.rowscale[gm1];
        }
        #pragma unroll
        for (int nt = 0; nt < 4; nt++) {
            int gn0 = bn + nw + nt * 8 + 2 * tig;
            int gn1 = gn0 + 1;
            #pragma unroll
            for (int q = 0; q < 4; q++) {
                int gm = (q < 2) ? gm0 : gm1;
                int gn = (q & 1) ? gn1 : gn0;
                if (gm >= p.M || gn >= p.N) continue;
                float v = acc[mt][nt][q] * ((q < 2) ? rs0 : rs1);
                if (EPI == 1 || EPI == 4) v = fmaxf(v, 0.f);
                else if (EPI == 2) v = 1.f / (1.f + __expf(-v));
                if (EPI >= 3) v = roundtf(v);
                p.C[(size_t)gm * p.ldc + gn] = v;
            }
        }
    }
}

static inline GemmP mk(const float* A, const float* B, float* C,
                       int M, int N, int K, int lda, int ldb, int ldc,
                       const float* rs) {
    GemmP p; p.A = A; p.B = B; p.C = C; p.M = M; p.N = N; p.K = K;
    p.lda = lda; p.ldb = ldb; p.ldc = ldc; p.rowscale = rs; return p;
}
static inline dim3 grid1(const GemmP& p) {
    return dim3((p.N + GBN - 1) / GBN, (p.M + GBM - 1) / GBM, 1);
}
static inline dim3 grid2(const GemmP& a, const GemmP& b, int zmul) {
    int gx = max((a.N + GBN - 1) / GBN, (b.N + GBN - 1) / GBN);
    int gy = max((a.M + GBM - 1) / GBM, (b.M + GBM - 1) / GBM);
    return dim3(gx, gy, 2 * zmul);
}
static inline dim3 tr_grid(int rows, int cols) {
    return dim3((cols + 31) / 32, (rows + 31) / 32);
}
static inline dim3 red_grid(const GemmP& a, const GemmP& b) {
    int n = max(a.N, b.N);
    int m = max(a.M, b.M);
    return dim3((n + 255) / 256, m, 2);
}

// ---------------- host orchestration ----------------
extern "C" void kernel_launch(void* const* d_in, const int* in_sizes, int n_in,
                              void* d_out, int out_size) {
    const float* R    = (const float*)d_in[0];
    const float* Dm   = (const float*)d_in[1];
    const float* Tm   = (const float*)d_in[2];
    const float* H_d  = (const float*)d_in[3];
    const float* H_t  = (const float*)d_in[4];
    const float* W1g[2] = {(const float*)d_in[5], (const float*)d_in[7]};
    const float* W2g[2] = {(const float*)d_in[6], (const float*)d_in[8]};
    const float* Wd[2]  = {(const float*)d_in[9], (const float*)d_in[11]};
    const float* Wt[2]  = {(const float*)d_in[10], (const float*)d_in[12]};
    const float* WdO  = (const float*)d_in[13];
    const float* WtO  = (const float*)d_in[14];
    float* out = (float*)d_out;

    float *S, *RT, *catd, *catt, *hdb, *htb, *hdp, *htp, *htpT;
    float *bsd, *bst, *bsd2, *bst2, *pa, *pb;
    float *sd, *st, *nd, *nt, *ntraw, *part, *selval;
    int* selidx;
    cudaGetSymbolAddress((void**)&S,     g_S);
    cudaGetSymbolAddress((void**)&RT,    g_RT);
    cudaGetSymbolAddress((void**)&catd,  g_catd);
    cudaGetSymbolAddress((void**)&catt,  g_catt);
    cudaGetSymbolAddress((void**)&hdb,   g_hd);
    cudaGetSymbolAddress((void**)&htb,   g_ht);
    cudaGetSymbolAddress((void**)&hdp,   g_hdp);
    cudaGetSymbolAddress((void**)&htp,   g_htp);
    cudaGetSymbolAddress((void**)&htpT,  g_htpT);
    cudaGetSymbolAddress((void**)&bsd,   g_bsd);
    cudaGetSymbolAddress((void**)&bst,   g_bst);
    cudaGetSymbolAddress((void**)&bsd2,  g_bsd2);
    cudaGetSymbolAddress((void**)&bst2,  g_bst2);
    cudaGetSymbolAddress((void**)&pa,    g_pa);
    cudaGetSymbolAddress((void**)&pb,    g_pb);
    cudaGetSymbolAddress((void**)&sd,    g_sd);
    cudaGetSymbolAddress((void**)&st,    g_st);
    cudaGetSymbolAddress((void**)&nd,    g_nd);
    cudaGetSymbolAddress((void**)&nt,    g_nt);
    cudaGetSymbolAddress((void**)&ntraw, g_ntraw);
    cudaGetSymbolAddress((void**)&part,  g_part);
    cudaGetSymbolAddress((void**)&selidx, g_selidx);
    cudaGetSymbolAddress((void**)&selval, g_selval);

    rowsum_rsqrt<<<D_NUM, 256>>>(Dm, D_NUM, D_NUM, sd);
    rowsum_rsqrt<<<T_NUM, 256>>>(Tm, T_NUM, T_NUM, st);

    const float* hd = H_d;
    const float* ht = H_t;
    int F = FEAT;

    for (int lvl = 0; lvl < 2; lvl++) {
        prescale2<<<dim3((F / 4 + 255) / 256, D_NUM, 2), 256>>>(
            bsd, hd, sd, D_NUM, bst, ht, st, T_NUM, F / 4);
        // split-K Dn/Tn
        {
            GemmP pD = mk(Dm, bsd, pa, D_NUM, F, D_NUM, D_NUM, F, F, nullptr);
            GemmP pT = mk(Tm, bst, pb, T_NUM, F, T_NUM, T_NUM, F, F, nullptr);
            mma_gemm_f<0, true, false, true><<<grid2(pD, pT, 2), GTHREADS>>>(pD, pT);
            reduce2<4><<<red_grid(pD, pT), 256>>>(
                catd + 2 * F, 3 * F, pa, sd, D_NUM, F,
                catt + 2 * F, 3 * F, pb, st, T_NUM, F);
        }
        // projections (small K, no split)
        {
            GemmP pd = mk(hd, W1g[lvl], hdp, D_NUM, UNITS, F, F, UNITS, UNITS, nullptr);
            GemmP pt = mk(ht, W2g[lvl], htp, T_NUM, UNITS, F, F, UNITS, UNITS, nullptr);
            mma_gemm_f<3, true, true, false><<<grid2(pd, pt, 1), GTHREADS>>>(pd, pt);
        }
        transpose_kernel<<<tr_grid(T_NUM, UNITS), dim3(32, 8)>>>(htpT, htp, T_NUM, UNITS);
        {
            GemmP ps = mk(hdp, htpT, S, D_NUM, T_NUM, UNITS, UNITS, T_NUM, T_NUM, nullptr);
            mma_gemm_f<2, false, false, false><<<grid1(ps), GTHREADS>>>(ps, ps);
        }

        zero_vec<<<(T_NUM + 255) / 256, 256>>>(ntraw, T_NUM);
        topk_kernel<<<D_NUM, 256>>>(S, selidx, selval, nd, ntraw);

        gather_dt<<<D_NUM, 256>>>(selidx, selval, nd, ntraw, ht, F, catd + F, 3 * F);
        zero_strided<<<dim3((F + 255) / 256, T_NUM), 256>>>(catt + F, 3 * F, T_NUM, F);
        scatter_td<<<D_NUM * TOPK, 256>>>(selidx, selval, nd, ntraw, hd, F, catt + F, 3 * F);
        relu_round_strided<<<dim3((F + 255) / 256, T_NUM), 256>>>(catt + F, 3 * F, T_NUM, F);
        copy_round2<<<dim3((F + 255) / 256, D_NUM, 2), 256>>>(
            catd, 3 * F, hd, F, D_NUM, catt, 3 * F, ht, F, T_NUM, F);

        // split-K concat dense (K = 3F = 768)
        {
            GemmP pd = mk(catd, Wd[lvl], pa, D_NUM, UNITS, 3 * F, 3 * F, UNITS, UNITS, nullptr);
            GemmP pt = mk(catt, Wt[lvl], pb, T_NUM, UNITS, 3 * F, 3 * F, UNITS, UNITS, nullptr);
            mma_gemm_f<0, false, true, true><<<grid2(pd, pt, 2), GTHREADS>>>(pd, pt);
            reduce2<1><<<red_grid(pd, pt), 256>>>(
                hdb, UNITS, pa, nullptr, D_NUM, UNITS,
                htb, UNITS, pb, nullptr, T_NUM, UNITS);
        }
        hd = hdb; ht = htb; F = UNITS;
    }

    // ---- output CGC on original (dense) R ----
    rowsum_rsqrt<<<D_NUM, 256>>>(R, D_NUM, T_NUM, nd);
    colsum_partial<<<dim3((T_NUM + 255) / 256, NCHUNK), 256>>>(R, D_NUM, T_NUM, part);
    colsum_finish<<<(T_NUM + 255) / 256, 256>>>(part, T_NUM, nt);
    transpose_kernel<<<tr_grid(D_NUM, T_NUM), dim3(32, 8)>>>(RT, R, D_NUM, T_NUM);

    prescale2<<<dim3((F / 4 + 255) / 256, D_NUM, 2), 256>>>(
        bsd, ht, nt, T_NUM, bst, hd, nd, D_NUM, F / 4);
    prescale2<<<dim3((F / 4 + 255) / 256, D_NUM, 2), 256>>>(
        bsd2, hd, sd, D_NUM, bst2, ht, st, T_NUM, F / 4);

    // split-K R-pair: H_dt = relu(Rn @ ht), H_td = relu(Rn^T @ hd)
    {
        GemmP pra = mk(R,  bsd, pa, D_NUM, F, T_NUM, T_NUM, F, F, nullptr);
        GemmP prb = mk(RT, bst, pb, T_NUM, F, D_NUM, D_NUM, F, F, nullptr);
        mma_gemm_f<0, true, false, true><<<grid2(pra, prb, 2), GTHREADS>>>(pra, prb);
        reduce2<4><<<red_grid(pra, prb), 256>>>(
            catd + F, 3 * F, pa, nd, D_NUM, F,
            catt + F, 3 * F, pb, nt, T_NUM, F);
    }
    // split-K Dn/Tn pair
    {
        GemmP pD = mk(Dm, bsd2, pa, D_NUM, F, D_NUM, D_NUM, F, F, nullptr);
        GemmP pT = mk(Tm, bst2, pb, T_NUM, F, T_NUM, T_NUM, F, F, nullptr);
        mma_gemm_f<0, true, false, true><<<grid2(pD, pT, 2), GTHREADS>>>(pD, pT);
        reduce2<4><<<red_grid(pD, pT), 256>>>(
            catd + 2 * F, 3 * F, pa, sd, D_NUM, F,
            catt + 2 * F, 3 * F, pb, st, T_NUM, F);
    }

    copy_round2<<<dim3((F + 255) / 256, D_NUM, 2), 256>>>(
        catd, 3 * F, hd, F, D_NUM, catt, 3 * F, ht, F, T_NUM, F);

    // split-K output dense (K = 600)
    {
        GemmP pd = mk(catd, WdO, pa, D_NUM, UNITS, 3 * F, 3 * F, UNITS, UNITS, nullptr);
        GemmP pt = mk(catt, WtO, pb, T_NUM, UNITS, 3 * F, 3 * F, UNITS, UNITS, nullptr);
        mma_gemm_f<0, false, true, true><<<grid2(pd, pt, 2), GTHREADS>>>(pd, pt);
        reduce2<4><<<red_grid(pd, pt), 256>>>(
            hdp, UNITS, pa, nullptr, D_NUM, UNITS,
            htp, UNITS, pb, nullptr, T_NUM, UNITS);
    }

    // R_pred = sigmoid(hd_out @ ht_out^T)
    transpose_kernel<<<tr_grid(T_NUM, UNITS), dim3(32, 8)>>>(htpT, htp, T_NUM, UNITS);
    {
        GemmP ps = mk(hdp, htpT, out, D_NUM, T_NUM, UNITS, UNITS, T_NUM, T_NUM, nullptr);
        mma_gemm_f<2, false, false, false><<<grid1(ps), GTHREADS>>>(ps, ps);
    }
}